// round 1
// baseline (speedup 1.0000x reference)
#include <cuda_runtime.h>
#include <math.h>
#include <stdint.h>

#define DD    160
#define QW    480      // 3*DD
#define NNODE 8192
#define PSZ   16
#define PNUM  512
#define MAXB  16

// ---------------- scratch (static device globals; no runtime allocation) ----
static __device__ float g_rex[(size_t)MAXB*NNODE*DD];   // residual stream
static __device__ float g_ln [(size_t)MAXB*NNODE*DD];   // LN output / orig buffer
static __device__ float g_tmp[(size_t)MAXB*NNODE*DD];   // attn out / mlp hidden
static __device__ float g_qkv[(size_t)MAXB*NNODE*QW];   // qkv projections

// ---------------------------------------------------------------- embed ----
// rex[b, j, :] for token j (already gathered through reo_all_idx)
__global__ void embed_kernel(const float* __restrict__ x, const int* __restrict__ te,
                             const int* __restrict__ reo_all,
                             const float* __restrict__ node_emb,
                             const float* __restrict__ tod_emb,
                             const float* __restrict__ dow_emb,
                             const float* __restrict__ in_w,
                             const float* __restrict__ in_b)
{
    int j = blockIdx.x, b = blockIdx.y, o = threadIdx.x;
    __shared__ float x1[12][3];
    int n = reo_all[j];
    if (o < 12) {
        int p = o;
        size_t base = ((size_t)(b*12 + p))*NNODE + n;
        x1[p][0] = x[base];
        x1[p][1] = (float)te[base*2 + 0] * (1.0f/288.0f);
        x1[p][2] = (float)te[base*2 + 1] * (1.0f/7.0f);
    }
    __syncthreads();
    float v;
    size_t tb = (((size_t)(b*12 + 11))*NNODE + n)*2;
    if (o < 64) {
        v = in_b[o];
        #pragma unroll
        for (int c = 0; c < 3; c++)
            #pragma unroll
            for (int p = 0; p < 12; p++)
                v += x1[p][c] * in_w[(c*12 + p)*64 + o];
    } else if (o < 96) {
        v = tod_emb[te[tb + 0]*32 + (o - 64)];
    } else if (o < 128) {
        v = dow_emb[te[tb + 1]*32 + (o - 96)];
    } else {
        v = node_emb[(size_t)n*32 + (o - 128)];
    }
    g_rex[((size_t)b*NNODE + j)*DD + o] = v;
}

// ------------------------------------------------------------- layernorm ----
__global__ void ln_kernel(const float* __restrict__ x, float* __restrict__ y, int M)
{
    int row  = blockIdx.x*8 + (threadIdx.x >> 5);
    int lane = threadIdx.x & 31;
    if (row >= M) return;
    const float* xr = x + (size_t)row*DD;
    float v[5]; float s = 0.f;
    #pragma unroll
    for (int j = 0; j < 5; j++) { v[j] = xr[lane + 32*j]; s += v[j]; }
    #pragma unroll
    for (int m = 16; m; m >>= 1) s += __shfl_xor_sync(0xffffffffu, s, m);
    float mean = s * (1.0f/160.0f);
    float q = 0.f;
    #pragma unroll
    for (int j = 0; j < 5; j++) { float d = v[j]-mean; q += d*d; }
    #pragma unroll
    for (int m = 16; m; m >>= 1) q += __shfl_xor_sync(0xffffffffu, q, m);
    float w = rsqrtf(q * (1.0f/160.0f) + 1e-6f);
    float* yr = y + (size_t)row*DD;
    #pragma unroll
    for (int j = 0; j < 5; j++) yr[lane + 32*j] = (v[j]-mean)*w;
}

// ------------------------------------------------------------------ gemm ----
// C[r, colbase+c] = op( A[r,:] @ W[:, colbase+c] + bias[colbase+c] )
// OP: 0 = bias, 1 = bias + residual, 2 = bias + exact gelu
template<int OP>
__global__ void __launch_bounds__(256) gemm_kernel(
    const float* __restrict__ A, const float* __restrict__ W,
    const float* __restrict__ bias, const float* __restrict__ Rsd,
    float* __restrict__ C, int ldw, int ldc)
{
    __shared__ float As[16][64];
    __shared__ float Bs[16][160];
    int tid = threadIdx.x;
    int row0 = blockIdx.x*64;
    int colbase = blockIdx.y*160;
    int ty = tid >> 5, tx = tid & 31;   // ty = warp id (rows), tx = lane (cols)
    float acc[8][5] = {};
    int lr = tid >> 2, lk4 = (tid & 3)*4;

    for (int k0 = 0; k0 < DD; k0 += 16) {
        float4 a4 = *(const float4*)(A + (size_t)(row0 + lr)*DD + k0 + lk4);
        As[lk4+0][lr] = a4.x; As[lk4+1][lr] = a4.y;
        As[lk4+2][lr] = a4.z; As[lk4+3][lr] = a4.w;
        for (int t = tid; t < 16*40; t += 256) {
            int kk = t/40, c4 = (t%40)*4;
            *(float4*)&Bs[kk][c4] =
                *(const float4*)(W + (size_t)(k0+kk)*ldw + colbase + c4);
        }
        __syncthreads();
        #pragma unroll
        for (int kk = 0; kk < 16; kk++) {
            float4 a0 = *(float4*)&As[kk][ty*8];
            float4 a1 = *(float4*)&As[kk][ty*8 + 4];
            float a[8] = {a0.x,a0.y,a0.z,a0.w,a1.x,a1.y,a1.z,a1.w};
            float bv[5];
            #pragma unroll
            for (int j = 0; j < 5; j++) bv[j] = Bs[kk][tx + 32*j];
            #pragma unroll
            for (int i = 0; i < 8; i++)
                #pragma unroll
                for (int j = 0; j < 5; j++)
                    acc[i][j] += a[i]*bv[j];
        }
        __syncthreads();
    }
    #pragma unroll
    for (int i = 0; i < 8; i++) {
        int r = row0 + ty*8 + i;
        #pragma unroll
        for (int j = 0; j < 5; j++) {
            int c = colbase + tx + 32*j;
            float v = acc[i][j] + bias[c];
            if (OP == 1) v += Rsd[(size_t)r*ldc + c];
            if (OP == 2) v = 0.5f*v*(1.0f + erff(v*0.70710678118654752f));
            C[(size_t)r*ldc + c] = v;
        }
    }
}

// ------------------------------------------------------ spatial attention ----
// one block per 16-token group; qkv rows are contiguous
__global__ void __launch_bounds__(256) spat_attn_kernel(const float* __restrict__ qkv,
                                                        float* __restrict__ out)
{
    __shared__ float Q[16][484];   // padded qkv tile (480 used)
    __shared__ float P[16][17];
    int g = blockIdx.x, tid = threadIdx.x;
    const float* src = qkv + (size_t)g*16*QW;
    for (int t = tid; t < 16*QW; t += 256) Q[t/QW][t%QW] = src[t];
    __syncthreads();
    int r = tid >> 4, c = tid & 15;
    float s = 0.f;
    #pragma unroll 8
    for (int k = 0; k < 160; k += 4) {
        float4 q4 = *(float4*)&Q[r][k];
        float4 k4 = *(float4*)&Q[c][160 + k];
        s += q4.x*k4.x + q4.y*k4.y + q4.z*k4.z + q4.w*k4.w;
    }
    s *= 0.07905694150420949f;   // 160^-0.5
    float m = s;
    #pragma unroll
    for (int msk = 8; msk; msk >>= 1) m = fmaxf(m, __shfl_xor_sync(0xffffffffu, m, msk));
    float p = expf(s - m);
    float sum = p;
    #pragma unroll
    for (int msk = 8; msk; msk >>= 1) sum += __shfl_xor_sync(0xffffffffu, sum, msk);
    P[r][c] = p / sum;
    __syncthreads();
    int c0 = (tid & 15)*10; r = tid >> 4;
    float acc[10] = {};
    #pragma unroll
    for (int j = 0; j < 16; j++) {
        float pv = P[r][j];
        #pragma unroll
        for (int q = 0; q < 10; q++) acc[q] += pv * Q[j][320 + c0 + q];
    }
    float* dst = out + (size_t)(g*16 + r)*DD + c0;
    #pragma unroll
    for (int q = 0; q < 10; q++) dst[q] = acc[q];
}

// --------------------------------------------------------- node attention ----
// group = (b, s): sequence over p in [0,512), token row = b*8192 + p*16 + s
// flash-style: 32 queries/block, stream K/V in 32-row tiles, online softmax
__global__ void __launch_bounds__(128) node_attn_kernel(const float* __restrict__ qkv,
                                                        float* __restrict__ out)
{
    __shared__ float Qs[32][164];
    __shared__ float KV[32][164];
    __shared__ float Ps[32][33];
    __shared__ float f_s[32], l_s[32];
    int qt = blockIdx.x;           // 16 query tiles
    int g  = blockIdx.y;           // b*16 + s
    int b = g >> 4, s = g & 15;
    int tid = threadIdx.x;
    const size_t rowstride = (size_t)PSZ*QW;   // between consecutive p
    size_t base = (size_t)b*NNODE*QW + (size_t)s*QW;
    const float scale = 0.07905694150420949f;

    for (int t = tid; t < 32*160; t += 128) {
        int r = t/160, c = t%160;
        Qs[r][c] = qkv[base + (size_t)(qt*32 + r)*rowstride + c] * scale;
    }
    float O[4][10] = {};
    float mrow[2] = {-3.0e38f, -3.0e38f};
    float lrow[2] = {0.f, 0.f};
    int rg = tid >> 3, cg = tid & 7;          // S tile: rows 2rg..2rg+1, cols cg+8j
    int ro = (tid >> 4)*4, co = (tid & 15)*10;// O tile

    for (int kt = 0; kt < 16; kt++) {
        __syncthreads();                       // prev O-update done (and Q ready)
        for (int t = tid; t < 32*160; t += 128) {
            int r = t/160, c = t%160;
            KV[r][c] = qkv[base + (size_t)(kt*32 + r)*rowstride + 160 + c];
        }
        __syncthreads();
        float sv[2][4] = {};
        #pragma unroll 4
        for (int k = 0; k < 160; k += 4) {
            float4 q0 = *(float4*)&Qs[2*rg][k];
            float4 q1 = *(float4*)&Qs[2*rg + 1][k];
            #pragma unroll
            for (int j = 0; j < 4; j++) {
                float4 k4 = *(float4*)&KV[cg + 8*j][k];
                sv[0][j] += q0.x*k4.x + q0.y*k4.y + q0.z*k4.z + q0.w*k4.w;
                sv[1][j] += q1.x*k4.x + q1.y*k4.y + q1.z*k4.z + q1.w*k4.w;
            }
        }
        #pragma unroll
        for (int ii = 0; ii < 2; ii++) {
            int r = 2*rg + ii;
            float mt = fmaxf(fmaxf(sv[ii][0], sv[ii][1]), fmaxf(sv[ii][2], sv[ii][3]));
            #pragma unroll
            for (int msk = 4; msk; msk >>= 1)
                mt = fmaxf(mt, __shfl_xor_sync(0xffffffffu, mt, msk));
            float mn = fmaxf(mrow[ii], mt);
            float f  = expf(mrow[ii] - mn);
            float sum = 0.f;
            #pragma unroll
            for (int j = 0; j < 4; j++) {
                float p = expf(sv[ii][j] - mn);
                Ps[r][cg + 8*j] = p;
                sum += p;
            }
            #pragma unroll
            for (int msk = 4; msk; msk >>= 1)
                sum += __shfl_xor_sync(0xffffffffu, sum, msk);
            lrow[ii] = lrow[ii]*f + sum;
            mrow[ii] = mn;
            if (cg == 0) f_s[r] = f;
        }
        __syncthreads();                       // Ps/f_s ready; K reads done
        for (int t = tid; t < 32*160; t += 128) {
            int r = t/160, c = t%160;
            KV[r][c] = qkv[base + (size_t)(kt*32 + r)*rowstride + 320 + c];
        }
        __syncthreads();
        float fo[4];
        #pragma unroll
        for (int i = 0; i < 4; i++) {
            fo[i] = f_s[ro + i];
            #pragma unroll
            for (int c = 0; c < 10; c++) O[i][c] *= fo[i];
        }
        #pragma unroll 2
        for (int j = 0; j < 32; j++) {
            float pv[4];
            #pragma unroll
            for (int i = 0; i < 4; i++) pv[i] = Ps[ro + i][j];
            #pragma unroll
            for (int c = 0; c < 10; c += 2) {
                float2 v2 = *(float2*)&KV[j][co + c];
                #pragma unroll
                for (int i = 0; i < 4; i++) {
                    O[i][c]   += pv[i]*v2.x;
                    O[i][c+1] += pv[i]*v2.y;
                }
            }
        }
    }
    if (cg == 0) { l_s[2*rg] = lrow[0]; l_s[2*rg + 1] = lrow[1]; }
    __syncthreads();
    #pragma unroll
    for (int i = 0; i < 4; i++) {
        float inv = 1.0f / l_s[ro + i];
        size_t orow = ((size_t)b*NNODE + (size_t)(qt*32 + ro + i)*PSZ + s)*DD + co;
        #pragma unroll
        for (int c = 0; c < 10; c++) out[orow + c] = O[i][c]*inv;
    }
}

// --------------------------------------------------- scatter / regression ----
__global__ void zero_kernel(float* p, size_t n)
{
    size_t i = (size_t)blockIdx.x*blockDim.x + threadIdx.x;
    if (i < n) p[i] = 0.f;
}

__global__ void scatter_kernel(const float* __restrict__ rex, float* __restrict__ orig,
                               const int* __restrict__ ori, const int* __restrict__ reo)
{
    int i = blockIdx.x, b = blockIdx.y, d = threadIdx.x;
    orig[((size_t)b*NNODE + ori[i])*DD + d] = rex[((size_t)b*NNODE + reo[i])*DD + d];
}

__global__ void __launch_bounds__(256) pred_kernel(const float* __restrict__ orig,
                                                   const float* __restrict__ reg_w,
                                                   const float* __restrict__ reg_b,
                                                   float* __restrict__ out)
{
    __shared__ float T[32][164];
    __shared__ float Wsh[12*160];
    int n0 = blockIdx.x*32, b = blockIdx.y, tid = threadIdx.x;
    for (int t = tid; t < 12*160; t += 256) Wsh[t] = reg_w[t];
    for (int t = tid; t < 32*160; t += 256)
        T[t/160][t%160] = orig[((size_t)b*NNODE + n0 + t/160)*DD + t%160];
    __syncthreads();
    for (int t = tid; t < 384; t += 256) {
        int o = t/32, nn = t%32;
        float acc = reg_b[o];
        #pragma unroll 8
        for (int d = 0; d < 160; d++) acc += Wsh[o*160 + d]*T[nn][d];
        out[((size_t)(b*12 + o))*NNODE + n0 + nn] = acc;
    }
}

// ---------------------------------------------------------------- launch ----
extern "C" void kernel_launch(void* const* d_in, const int* in_sizes, int n_in,
                              void* d_out, int out_size)
{
    const float* x        = (const float*)d_in[0];
    const int*   te       = (const int*)  d_in[1];
    const int*   reo_all  = (const int*)  d_in[2];
    const int*   ori_p    = (const int*)  d_in[3];
    const int*   reo_p    = (const int*)  d_in[4];
    const float* node_emb = (const float*)d_in[5];
    const float* tod_emb  = (const float*)d_in[6];
    const float* dow_emb  = (const float*)d_in[7];
    const float* in_w     = (const float*)d_in[8];
    const float* in_b     = (const float*)d_in[9];
    const float* qkv_s_w  = (const float*)d_in[10];
    const float* qkv_s_b  = (const float*)d_in[11];
    const float* proj_s_w = (const float*)d_in[12];
    const float* proj_s_b = (const float*)d_in[13];
    const float* fc1_s_w  = (const float*)d_in[14];
    const float* fc1_s_b  = (const float*)d_in[15];
    const float* fc2_s_w  = (const float*)d_in[16];
    const float* fc2_s_b  = (const float*)d_in[17];
    const float* qkv_n_w  = (const float*)d_in[18];
    const float* qkv_n_b  = (const float*)d_in[19];
    const float* proj_n_w = (const float*)d_in[20];
    const float* proj_n_b = (const float*)d_in[21];
    const float* fc1_n_w  = (const float*)d_in[22];
    const float* fc1_n_b  = (const float*)d_in[23];
    const float* fc2_n_w  = (const float*)d_in[24];
    const float* fc2_n_b  = (const float*)d_in[25];
    const float* reg_w    = (const float*)d_in[26];
    const float* reg_b    = (const float*)d_in[27];
    float* out = (float*)d_out;

    int B = in_sizes[0] / (12*NNODE);
    int M = B*NNODE;

    float *rex, *ln, *tmp, *qkv;
    cudaGetSymbolAddress((void**)&rex, g_rex);
    cudaGetSymbolAddress((void**)&ln,  g_ln);
    cudaGetSymbolAddress((void**)&tmp, g_tmp);
    cudaGetSymbolAddress((void**)&qkv, g_qkv);

    embed_kernel<<<dim3(NNODE, B), DD>>>(x, te, reo_all, node_emb, tod_emb, dow_emb,
                                         in_w, in_b);

    for (int l = 0; l < 3; l++) {
        size_t oW3 = (size_t)l*DD*QW, ob3 = (size_t)l*QW;
        size_t oW1 = (size_t)l*DD*DD, ob1 = (size_t)l*DD;

        // --- spatial attention block ---
        ln_kernel<<<M/8, 256>>>(rex, ln, M);
        gemm_kernel<0><<<dim3(M/64, 3), 256>>>(ln, qkv_s_w + oW3, qkv_s_b + ob3,
                                               nullptr, qkv, QW, QW);
        spat_attn_kernel<<<M/16, 256>>>(qkv, tmp);
        gemm_kernel<1><<<dim3(M/64, 1), 256>>>(tmp, proj_s_w + oW1, proj_s_b + ob1,
                                               rex, rex, DD, DD);
        // --- spatial MLP ---
        ln_kernel<<<M/8, 256>>>(rex, ln, M);
        gemm_kernel<2><<<dim3(M/64, 1), 256>>>(ln, fc1_s_w + oW1, fc1_s_b + ob1,
                                               nullptr, tmp, DD, DD);
        gemm_kernel<1><<<dim3(M/64, 1), 256>>>(tmp, fc2_s_w + oW1, fc2_s_b + ob1,
                                               rex, rex, DD, DD);
        // --- node attention block ---
        ln_kernel<<<M/8, 256>>>(rex, ln, M);
        gemm_kernel<0><<<dim3(M/64, 3), 256>>>(ln, qkv_n_w + oW3, qkv_n_b + ob3,
                                               nullptr, qkv, QW, QW);
        node_attn_kernel<<<dim3(PNUM/32, B*PSZ), 128>>>(qkv, tmp);
        gemm_kernel<1><<<dim3(M/64, 1), 256>>>(tmp, proj_n_w + oW1, proj_n_b + ob1,
                                               rex, rex, DD, DD);
        // --- node MLP ---
        ln_kernel<<<M/8, 256>>>(rex, ln, M);
        gemm_kernel<2><<<dim3(M/64, 1), 256>>>(ln, fc1_n_w + oW1, fc1_n_b + ob1,
                                               nullptr, tmp, DD, DD);
        gemm_kernel<1><<<dim3(M/64, 1), 256>>>(tmp, fc2_n_w + oW1, fc2_n_b + ob1,
                                               rex, rex, DD, DD);
    }

    // scatter back to original node order (general indices), then regression head
    size_t tot = (size_t)M*DD;
    zero_kernel<<<(unsigned)((tot + 255)/256), 256>>>(ln, tot);
    scatter_kernel<<<dim3(NNODE, B), DD>>>(rex, ln, ori_p, reo_p);
    pred_kernel<<<dim3(NNODE/32, B), 256>>>(ln, reg_w, reg_b, out);
}

// round 2
// speedup vs baseline: 1.0005x; 1.0005x over previous
#include <cuda_runtime.h>
#include <math.h>
#include <stdint.h>

#define DD    160
#define QW    480      // 3*DD
#define NNODE 8192
#define PSZ   16
#define PNUM  512
#define MAXB  16

// ---------------- scratch (static device globals; no runtime allocation) ----
static __device__ float g_rex[(size_t)MAXB*NNODE*DD];   // residual stream
static __device__ float g_ln [(size_t)MAXB*NNODE*DD];   // LN output / orig buffer
static __device__ float g_tmp[(size_t)MAXB*NNODE*DD];   // attn out / mlp hidden
static __device__ float g_qkv[(size_t)MAXB*NNODE*QW];   // qkv projections

// ---------------------------------------------------------------- embed ----
// rex[b, j, :] for token j (already gathered through reo_all_idx)
__global__ void embed_kernel(const float* __restrict__ x, const int* __restrict__ te,
                             const int* __restrict__ reo_all,
                             const float* __restrict__ node_emb,
                             const float* __restrict__ tod_emb,
                             const float* __restrict__ dow_emb,
                             const float* __restrict__ in_w,
                             const float* __restrict__ in_b)
{
    int j = blockIdx.x, b = blockIdx.y, o = threadIdx.x;
    __shared__ float x1[12][3];
    int n = reo_all[j];
    if (o < 12) {
        int p = o;
        size_t base = ((size_t)(b*12 + p))*NNODE + n;
        x1[p][0] = x[base];
        x1[p][1] = (float)te[base*2 + 0] * (1.0f/288.0f);
        x1[p][2] = (float)te[base*2 + 1] * (1.0f/7.0f);
    }
    __syncthreads();
    float v;
    size_t tb = (((size_t)(b*12 + 11))*NNODE + n)*2;
    if (o < 64) {
        v = in_b[o];
        #pragma unroll
        for (int c = 0; c < 3; c++)
            #pragma unroll
            for (int p = 0; p < 12; p++)
                v += x1[p][c] * in_w[(c*12 + p)*64 + o];
    } else if (o < 96) {
        v = tod_emb[te[tb + 0]*32 + (o - 64)];
    } else if (o < 128) {
        v = dow_emb[te[tb + 1]*32 + (o - 96)];
    } else {
        v = node_emb[(size_t)n*32 + (o - 128)];
    }
    g_rex[((size_t)b*NNODE + j)*DD + o] = v;
}

// ------------------------------------------------------------- layernorm ----
__global__ void ln_kernel(const float* __restrict__ x, float* __restrict__ y, int M)
{
    int row  = blockIdx.x*8 + (threadIdx.x >> 5);
    int lane = threadIdx.x & 31;
    if (row >= M) return;
    const float* xr = x + (size_t)row*DD;
    float v[5]; float s = 0.f;
    #pragma unroll
    for (int j = 0; j < 5; j++) { v[j] = xr[lane + 32*j]; s += v[j]; }
    #pragma unroll
    for (int m = 16; m; m >>= 1) s += __shfl_xor_sync(0xffffffffu, s, m);
    float mean = s * (1.0f/160.0f);
    float q = 0.f;
    #pragma unroll
    for (int j = 0; j < 5; j++) { float d = v[j]-mean; q += d*d; }
    #pragma unroll
    for (int m = 16; m; m >>= 1) q += __shfl_xor_sync(0xffffffffu, q, m);
    float w = rsqrtf(q * (1.0f/160.0f) + 1e-6f);
    float* yr = y + (size_t)row*DD;
    #pragma unroll
    for (int j = 0; j < 5; j++) yr[lane + 32*j] = (v[j]-mean)*w;
}

// ------------------------------------------------------------------ gemm ----
// C[r, colbase+c] = op( A[r,:] @ W[:, colbase+c] + bias[colbase+c] )
// OP: 0 = bias, 1 = bias + residual, 2 = bias + exact gelu
template<int OP>
__global__ void __launch_bounds__(256) gemm_kernel(
    const float* __restrict__ A, const float* __restrict__ W,
    const float* __restrict__ bias, const float* __restrict__ Rsd,
    float* __restrict__ C, int ldw, int ldc)
{
    __shared__ float As[16][64];
    __shared__ float Bs[16][160];
    int tid = threadIdx.x;
    int row0 = blockIdx.x*64;
    int colbase = blockIdx.y*160;
    int ty = tid >> 5, tx = tid & 31;   // ty = warp id (rows), tx = lane (cols)
    float acc[8][5] = {};
    int lr = tid >> 2, lk4 = (tid & 3)*4;

    for (int k0 = 0; k0 < DD; k0 += 16) {
        float4 a4 = *(const float4*)(A + (size_t)(row0 + lr)*DD + k0 + lk4);
        As[lk4+0][lr] = a4.x; As[lk4+1][lr] = a4.y;
        As[lk4+2][lr] = a4.z; As[lk4+3][lr] = a4.w;
        for (int t = tid; t < 16*40; t += 256) {
            int kk = t/40, c4 = (t%40)*4;
            *(float4*)&Bs[kk][c4] =
                *(const float4*)(W + (size_t)(k0+kk)*ldw + colbase + c4);
        }
        __syncthreads();
        #pragma unroll
        for (int kk = 0; kk < 16; kk++) {
            float4 a0 = *(float4*)&As[kk][ty*8];
            float4 a1 = *(float4*)&As[kk][ty*8 + 4];
            float a[8] = {a0.x,a0.y,a0.z,a0.w,a1.x,a1.y,a1.z,a1.w};
            float bv[5];
            #pragma unroll
            for (int j = 0; j < 5; j++) bv[j] = Bs[kk][tx + 32*j];
            #pragma unroll
            for (int i = 0; i < 8; i++)
                #pragma unroll
                for (int j = 0; j < 5; j++)
                    acc[i][j] += a[i]*bv[j];
        }
        __syncthreads();
    }
    #pragma unroll
    for (int i = 0; i < 8; i++) {
        int r = row0 + ty*8 + i;
        #pragma unroll
        for (int j = 0; j < 5; j++) {
            int c = colbase + tx + 32*j;
            float v = acc[i][j] + bias[c];
            if (OP == 1) v += Rsd[(size_t)r*ldc + c];
            if (OP == 2) v = 0.5f*v*(1.0f + erff(v*0.70710678118654752f));
            C[(size_t)r*ldc + c] = v;
        }
    }
}

// ------------------------------------------------------ spatial attention ----
// one block per 16-token group; qkv rows are contiguous
__global__ void __launch_bounds__(256) spat_attn_kernel(const float* __restrict__ qkv,
                                                        float* __restrict__ out)
{
    __shared__ float Q[16][484];   // padded qkv tile (480 used)
    __shared__ float P[16][17];
    int g = blockIdx.x, tid = threadIdx.x;
    const float* src = qkv + (size_t)g*16*QW;
    for (int t = tid; t < 16*QW; t += 256) Q[t/QW][t%QW] = src[t];
    __syncthreads();
    int r = tid >> 4, c = tid & 15;
    float s = 0.f;
    #pragma unroll 8
    for (int k = 0; k < 160; k += 4) {
        float4 q4 = *(float4*)&Q[r][k];
        float4 k4 = *(float4*)&Q[c][160 + k];
        s += q4.x*k4.x + q4.y*k4.y + q4.z*k4.z + q4.w*k4.w;
    }
    s *= 0.07905694150420949f;   // 160^-0.5
    float m = s;
    #pragma unroll
    for (int msk = 8; msk; msk >>= 1) m = fmaxf(m, __shfl_xor_sync(0xffffffffu, m, msk));
    float p = expf(s - m);
    float sum = p;
    #pragma unroll
    for (int msk = 8; msk; msk >>= 1) sum += __shfl_xor_sync(0xffffffffu, sum, msk);
    P[r][c] = p / sum;
    __syncthreads();
    int c0 = (tid & 15)*10; r = tid >> 4;
    float acc[10] = {};
    #pragma unroll
    for (int j = 0; j < 16; j++) {
        float pv = P[r][j];
        #pragma unroll
        for (int q = 0; q < 10; q++) acc[q] += pv * Q[j][320 + c0 + q];
    }
    float* dst = out + (size_t)(g*16 + r)*DD + c0;
    #pragma unroll
    for (int q = 0; q < 10; q++) dst[q] = acc[q];
}

// --------------------------------------------------------- node attention ----
// group = (b, s): sequence over p in [0,512), token row = b*8192 + p*16 + s
// flash-style: 32 queries/block, stream K/V in 32-row tiles, online softmax
__global__ void __launch_bounds__(128) node_attn_kernel(const float* __restrict__ qkv,
                                                        float* __restrict__ out)
{
    __shared__ float Qs[32][164];
    __shared__ float KV[32][164];
    __shared__ float Ps[32][33];
    __shared__ float f_s[32], l_s[32];
    int qt = blockIdx.x;           // 16 query tiles
    int g  = blockIdx.y;           // b*16 + s
    int b = g >> 4, s = g & 15;
    int tid = threadIdx.x;
    const size_t rowstride = (size_t)PSZ*QW;   // between consecutive p
    size_t base = (size_t)b*NNODE*QW + (size_t)s*QW;
    const float scale = 0.07905694150420949f;

    for (int t = tid; t < 32*160; t += 128) {
        int r = t/160, c = t%160;
        Qs[r][c] = qkv[base + (size_t)(qt*32 + r)*rowstride + c] * scale;
    }
    float O[4][10] = {};
    float mrow[2] = {-3.0e38f, -3.0e38f};
    float lrow[2] = {0.f, 0.f};
    int rg = tid >> 3, cg = tid & 7;          // S tile: rows 2rg..2rg+1, cols cg+8j
    int ro = (tid >> 4)*4, co = (tid & 15)*10;// O tile

    for (int kt = 0; kt < 16; kt++) {
        __syncthreads();                       // prev O-update done (and Q ready)
        for (int t = tid; t < 32*160; t += 128) {
            int r = t/160, c = t%160;
            KV[r][c] = qkv[base + (size_t)(kt*32 + r)*rowstride + 160 + c];
        }
        __syncthreads();
        float sv[2][4] = {};
        #pragma unroll 4
        for (int k = 0; k < 160; k += 4) {
            float4 q0 = *(float4*)&Qs[2*rg][k];
            float4 q1 = *(float4*)&Qs[2*rg + 1][k];
            #pragma unroll
            for (int j = 0; j < 4; j++) {
                float4 k4 = *(float4*)&KV[cg + 8*j][k];
                sv[0][j] += q0.x*k4.x + q0.y*k4.y + q0.z*k4.z + q0.w*k4.w;
                sv[1][j] += q1.x*k4.x + q1.y*k4.y + q1.z*k4.z + q1.w*k4.w;
            }
        }
        #pragma unroll
        for (int ii = 0; ii < 2; ii++) {
            int r = 2*rg + ii;
            float mt = fmaxf(fmaxf(sv[ii][0], sv[ii][1]), fmaxf(sv[ii][2], sv[ii][3]));
            #pragma unroll
            for (int msk = 4; msk; msk >>= 1)
                mt = fmaxf(mt, __shfl_xor_sync(0xffffffffu, mt, msk));
            float mn = fmaxf(mrow[ii], mt);
            float f  = expf(mrow[ii] - mn);
            float sum = 0.f;
            #pragma unroll
            for (int j = 0; j < 4; j++) {
                float p = expf(sv[ii][j] - mn);
                Ps[r][cg + 8*j] = p;
                sum += p;
            }
            #pragma unroll
            for (int msk = 4; msk; msk >>= 1)
                sum += __shfl_xor_sync(0xffffffffu, sum, msk);
            lrow[ii] = lrow[ii]*f + sum;
            mrow[ii] = mn;
            if (cg == 0) f_s[r] = f;
        }
        __syncthreads();                       // Ps/f_s ready; K reads done
        for (int t = tid; t < 32*160; t += 128) {
            int r = t/160, c = t%160;
            KV[r][c] = qkv[base + (size_t)(kt*32 + r)*rowstride + 320 + c];
        }
        __syncthreads();
        float fo[4];
        #pragma unroll
        for (int i = 0; i < 4; i++) {
            fo[i] = f_s[ro + i];
            #pragma unroll
            for (int c = 0; c < 10; c++) O[i][c] *= fo[i];
        }
        #pragma unroll 2
        for (int j = 0; j < 32; j++) {
            float pv[4];
            #pragma unroll
            for (int i = 0; i < 4; i++) pv[i] = Ps[ro + i][j];
            #pragma unroll
            for (int c = 0; c < 10; c += 2) {
                float2 v2 = *(float2*)&KV[j][co + c];
                #pragma unroll
                for (int i = 0; i < 4; i++) {
                    O[i][c]   += pv[i]*v2.x;
                    O[i][c+1] += pv[i]*v2.y;
                }
            }
        }
    }
    if (cg == 0) { l_s[2*rg] = lrow[0]; l_s[2*rg + 1] = lrow[1]; }
    __syncthreads();
    #pragma unroll
    for (int i = 0; i < 4; i++) {
        float inv = 1.0f / l_s[ro + i];
        size_t orow = ((size_t)b*NNODE + (size_t)(qt*32 + ro + i)*PSZ + s)*DD + co;
        #pragma unroll
        for (int c = 0; c < 10; c++) out[orow + c] = O[i][c]*inv;
    }
}

// --------------------------------------------------- scatter / regression ----
__global__ void zero_kernel(float* p, size_t n)
{
    size_t i = (size_t)blockIdx.x*blockDim.x + threadIdx.x;
    if (i < n) p[i] = 0.f;
}

__global__ void scatter_kernel(const float* __restrict__ rex, float* __restrict__ orig,
                               const int* __restrict__ ori, const int* __restrict__ reo)
{
    int i = blockIdx.x, b = blockIdx.y, d = threadIdx.x;
    orig[((size_t)b*NNODE + ori[i])*DD + d] = rex[((size_t)b*NNODE + reo[i])*DD + d];
}

__global__ void __launch_bounds__(256) pred_kernel(const float* __restrict__ orig,
                                                   const float* __restrict__ reg_w,
                                                   const float* __restrict__ reg_b,
                                                   float* __restrict__ out)
{
    __shared__ float T[32][164];
    __shared__ float Wsh[12*160];
    int n0 = blockIdx.x*32, b = blockIdx.y, tid = threadIdx.x;
    for (int t = tid; t < 12*160; t += 256) Wsh[t] = reg_w[t];
    for (int t = tid; t < 32*160; t += 256)
        T[t/160][t%160] = orig[((size_t)b*NNODE + n0 + t/160)*DD + t%160];
    __syncthreads();
    for (int t = tid; t < 384; t += 256) {
        int o = t/32, nn = t%32;
        float acc = reg_b[o];
        #pragma unroll 8
        for (int d = 0; d < 160; d++) acc += Wsh[o*160 + d]*T[nn][d];
        out[((size_t)(b*12 + o))*NNODE + n0 + nn] = acc;
    }
}

// ---------------------------------------------------------------- launch ----
extern "C" void kernel_launch(void* const* d_in, const int* in_sizes, int n_in,
                              void* d_out, int out_size)
{
    const float* x        = (const float*)d_in[0];
    const int*   te       = (const int*)  d_in[1];
    const int*   reo_all  = (const int*)  d_in[2];
    const int*   ori_p    = (const int*)  d_in[3];
    const int*   reo_p    = (const int*)  d_in[4];
    const float* node_emb = (const float*)d_in[5];
    const float* tod_emb  = (const float*)d_in[6];
    const float* dow_emb  = (const float*)d_in[7];
    const float* in_w     = (const float*)d_in[8];
    const float* in_b     = (const float*)d_in[9];
    const float* qkv_s_w  = (const float*)d_in[10];
    const float* qkv_s_b  = (const float*)d_in[11];
    const float* proj_s_w = (const float*)d_in[12];
    const float* proj_s_b = (const float*)d_in[13];
    const float* fc1_s_w  = (const float*)d_in[14];
    const float* fc1_s_b  = (const float*)d_in[15];
    const float* fc2_s_w  = (const float*)d_in[16];
    const float* fc2_s_b  = (const float*)d_in[17];
    const float* qkv_n_w  = (const float*)d_in[18];
    const float* qkv_n_b  = (const float*)d_in[19];
    const float* proj_n_w = (const float*)d_in[20];
    const float* proj_n_b = (const float*)d_in[21];
    const float* fc1_n_w  = (const float*)d_in[22];
    const float* fc1_n_b  = (const float*)d_in[23];
    const float* fc2_n_w  = (const float*)d_in[24];
    const float* fc2_n_b  = (const float*)d_in[25];
    const float* reg_w    = (const float*)d_in[26];
    const float* reg_b    = (const float*)d_in[27];
    float* out = (float*)d_out;

    int B = in_sizes[0] / (12*NNODE);
    int M = B*NNODE;

    float *rex, *ln, *tmp, *qkv;
    cudaGetSymbolAddress((void**)&rex, g_rex);
    cudaGetSymbolAddress((void**)&ln,  g_ln);
    cudaGetSymbolAddress((void**)&tmp, g_tmp);
    cudaGetSymbolAddress((void**)&qkv, g_qkv);

    embed_kernel<<<dim3(NNODE, B), DD>>>(x, te, reo_all, node_emb, tod_emb, dow_emb,
                                         in_w, in_b);

    for (int l = 0; l < 3; l++) {
        size_t oW3 = (size_t)l*DD*QW, ob3 = (size_t)l*QW;
        size_t oW1 = (size_t)l*DD*DD, ob1 = (size_t)l*DD;

        // --- spatial attention block ---
        ln_kernel<<<M/8, 256>>>(rex, ln, M);
        gemm_kernel<0><<<dim3(M/64, 3), 256>>>(ln, qkv_s_w + oW3, qkv_s_b + ob3,
                                               nullptr, qkv, QW, QW);
        spat_attn_kernel<<<M/16, 256>>>(qkv, tmp);
        gemm_kernel<1><<<dim3(M/64, 1), 256>>>(tmp, proj_s_w + oW1, proj_s_b + ob1,
                                               rex, rex, DD, DD);
        // --- spatial MLP ---
        ln_kernel<<<M/8, 256>>>(rex, ln, M);
        gemm_kernel<2><<<dim3(M/64, 1), 256>>>(ln, fc1_s_w + oW1, fc1_s_b + ob1,
                                               nullptr, tmp, DD, DD);
        gemm_kernel<1><<<dim3(M/64, 1), 256>>>(tmp, fc2_s_w + oW1, fc2_s_b + ob1,
                                               rex, rex, DD, DD);
        // --- node attention block ---
        ln_kernel<<<M/8, 256>>>(rex, ln, M);
        gemm_kernel<0><<<dim3(M/64, 3), 256>>>(ln, qkv_n_w + oW3, qkv_n_b + ob3,
                                               nullptr, qkv, QW, QW);
        node_attn_kernel<<<dim3(PNUM/32, B*PSZ), 128>>>(qkv, tmp);
        gemm_kernel<1><<<dim3(M/64, 1), 256>>>(tmp, proj_n_w + oW1, proj_n_b + ob1,
                                               rex, rex, DD, DD);
        // --- node MLP ---
        ln_kernel<<<M/8, 256>>>(rex, ln, M);
        gemm_kernel<2><<<dim3(M/64, 1), 256>>>(ln, fc1_n_w + oW1, fc1_n_b + ob1,
                                               nullptr, tmp, DD, DD);
        gemm_kernel<1><<<dim3(M/64, 1), 256>>>(tmp, fc2_n_w + oW1, fc2_n_b + ob1,
                                               rex, rex, DD, DD);
    }

    // scatter back to original node order (general indices), then regression head
    size_t tot = (size_t)M*DD;
    zero_kernel<<<(unsigned)((tot + 255)/256), 256>>>(ln, tot);
    scatter_kernel<<<dim3(NNODE, B), DD>>>(rex, ln, ori_p, reo_p);
    pred_kernel<<<dim3(NNODE/32, B), 256>>>(ln, reg_w, reg_b, out);
}

// round 3
// speedup vs baseline: 1.2953x; 1.2946x over previous
#include <cuda_runtime.h>
#include <math.h>
#include <stdint.h>

#define DD    160
#define QW    480      // 3*DD
#define NNODE 8192
#define PSZ   16
#define PNUM  512
#define MAXB  16

// ---------------- scratch (static device globals; no runtime allocation) ----
static __device__ float g_rex[(size_t)MAXB*NNODE*DD];   // residual stream
static __device__ float g_ln [(size_t)MAXB*NNODE*DD];   // LN output / orig buffer
static __device__ float g_tmp[(size_t)MAXB*NNODE*DD];   // attn out / mlp hidden
static __device__ float g_qkv[(size_t)MAXB*NNODE*QW];   // qkv projections

// ---------------------------------------------------------------- embed ----
__global__ void embed_kernel(const float* __restrict__ x, const int* __restrict__ te,
                             const int* __restrict__ reo_all,
                             const float* __restrict__ node_emb,
                             const float* __restrict__ tod_emb,
                             const float* __restrict__ dow_emb,
                             const float* __restrict__ in_w,
                             const float* __restrict__ in_b)
{
    int j = blockIdx.x, b = blockIdx.y, o = threadIdx.x;
    __shared__ float x1[12][3];
    int n = reo_all[j];
    if (o < 12) {
        int p = o;
        size_t base = ((size_t)(b*12 + p))*NNODE + n;
        x1[p][0] = x[base];
        x1[p][1] = (float)te[base*2 + 0] * (1.0f/288.0f);
        x1[p][2] = (float)te[base*2 + 1] * (1.0f/7.0f);
    }
    __syncthreads();
    float v;
    size_t tb = (((size_t)(b*12 + 11))*NNODE + n)*2;
    if (o < 64) {
        v = in_b[o];
        #pragma unroll
        for (int c = 0; c < 3; c++)
            #pragma unroll
            for (int p = 0; p < 12; p++)
                v += x1[p][c] * in_w[(c*12 + p)*64 + o];
    } else if (o < 96) {
        v = tod_emb[te[tb + 0]*32 + (o - 64)];
    } else if (o < 128) {
        v = dow_emb[te[tb + 1]*32 + (o - 96)];
    } else {
        v = node_emb[(size_t)n*32 + (o - 128)];
    }
    g_rex[((size_t)b*NNODE + j)*DD + o] = v;
}

// ------------------------------------------------------------- layernorm ----
__global__ void ln_kernel(const float* __restrict__ x, float* __restrict__ y, int M)
{
    int row  = blockIdx.x*8 + (threadIdx.x >> 5);
    int lane = threadIdx.x & 31;
    if (row >= M) return;
    const float* xr = x + (size_t)row*DD;
    float v[5]; float s = 0.f;
    #pragma unroll
    for (int j = 0; j < 5; j++) { v[j] = xr[lane + 32*j]; s += v[j]; }
    #pragma unroll
    for (int m = 16; m; m >>= 1) s += __shfl_xor_sync(0xffffffffu, s, m);
    float mean = s * (1.0f/160.0f);
    float q = 0.f;
    #pragma unroll
    for (int j = 0; j < 5; j++) { float d = v[j]-mean; q += d*d; }
    #pragma unroll
    for (int m = 16; m; m >>= 1) q += __shfl_xor_sync(0xffffffffu, q, m);
    float w = rsqrtf(q * (1.0f/160.0f) + 1e-6f);
    float* yr = y + (size_t)row*DD;
    #pragma unroll
    for (int j = 0; j < 5; j++) yr[lane + 32*j] = (v[j]-mean)*w;
}

// ------------------------------------------------------------ tf32 mma  ----
__device__ __forceinline__ unsigned f2tf32(float f)
{
    unsigned r;
    asm("cvt.rna.tf32.f32 %0, %1;" : "=r"(r) : "f"(f));
    return r;
}

__device__ __forceinline__ void mma_tf32(float* c, const unsigned* a, const unsigned* b)
{
    asm volatile(
        "mma.sync.aligned.m16n8k8.row.col.f32.tf32.tf32.f32 "
        "{%0,%1,%2,%3}, {%4,%5,%6,%7}, {%8,%9}, {%0,%1,%2,%3};\n"
        : "+f"(c[0]), "+f"(c[1]), "+f"(c[2]), "+f"(c[3])
        : "r"(a[0]), "r"(a[1]), "r"(a[2]), "r"(a[3]), "r"(b[0]), "r"(b[1]));
}

// ------------------------------------------------------------------ gemm ----
// C[r, colbase+c] = op( A[r,:DD] @ W[:, colbase+c] + bias[colbase+c] )
// OP: 0 = bias, 1 = bias + residual, 2 = bias + exact gelu
// tile: 128 rows x 160 cols, K-tiles of 32; 8 warps = 2(m) x 4(n)
template<int OP>
__global__ void __launch_bounds__(256) gemm_mma_kernel(
    const float* __restrict__ A, const float* __restrict__ W,
    const float* __restrict__ bias, const float* __restrict__ Rsd,
    float* __restrict__ C, int ldw, int ldc)
{
    __shared__ unsigned As[128][36];   // stride 36: frag reads conflict-free
    __shared__ unsigned Bs[160][36];   // Bs[n][k]  (W transposed for row.col)
    int tid  = threadIdx.x;
    int lane = tid & 31, wid = tid >> 5;
    int warp_m = wid >> 2, warp_n = wid & 3;
    int row0 = blockIdx.x*128, colbase = blockIdx.y*160;

    float acc[4][5][4] = {};
    int ar = tid >> 1, ac = (tid & 1)*16;

    for (int k0 = 0; k0 < DD; k0 += 32) {
        #pragma unroll
        for (int q = 0; q < 4; q++) {
            float4 a4 = *(const float4*)(A + (size_t)(row0 + ar)*DD + k0 + ac + q*4);
            As[ar][ac + q*4 + 0] = f2tf32(a4.x);
            As[ar][ac + q*4 + 1] = f2tf32(a4.y);
            As[ar][ac + q*4 + 2] = f2tf32(a4.z);
            As[ar][ac + q*4 + 3] = f2tf32(a4.w);
        }
        #pragma unroll
        for (int it = 0; it < 20; it++) {
            int idx = tid + it*256;
            int kk = idx / 160, n = idx - kk*160;
            Bs[n][kk] = f2tf32(W[(size_t)(k0 + kk)*ldw + colbase + n]);
        }
        __syncthreads();
        #pragma unroll
        for (int ks = 0; ks < 4; ks++) {
            unsigned af[4][4], bf[5][2];
            int arow = warp_m*64 + (lane >> 2);
            int kc   = ks*8 + (lane & 3);
            #pragma unroll
            for (int i = 0; i < 4; i++) {
                af[i][0] = As[arow + i*16    ][kc];
                af[i][1] = As[arow + i*16 + 8][kc];
                af[i][2] = As[arow + i*16    ][kc + 4];
                af[i][3] = As[arow + i*16 + 8][kc + 4];
            }
            int bn = warp_n*40 + (lane >> 2);
            #pragma unroll
            for (int j = 0; j < 5; j++) {
                bf[j][0] = Bs[bn + j*8][kc];
                bf[j][1] = Bs[bn + j*8][kc + 4];
            }
            #pragma unroll
            for (int i = 0; i < 4; i++)
                #pragma unroll
                for (int j = 0; j < 5; j++)
                    mma_tf32(acc[i][j], af[i], bf[j]);
        }
        __syncthreads();
    }

    // epilogue: each (i,j) frag owns rows {r, r+8}, cols {c, c+1}
    int rw = row0 + warp_m*64 + (lane >> 2);
    int cw = colbase + warp_n*40 + 2*(lane & 3);
    #pragma unroll
    for (int j = 0; j < 5; j++) {
        int c = cw + j*8;
        float b0 = bias[c], b1 = bias[c + 1];
        #pragma unroll
        for (int i = 0; i < 4; i++) {
            #pragma unroll
            for (int h = 0; h < 2; h++) {
                int r = rw + i*16 + h*8;
                float v0 = acc[i][j][2*h + 0] + b0;
                float v1 = acc[i][j][2*h + 1] + b1;
                if (OP == 1) {
                    float2 rs = *(const float2*)(Rsd + (size_t)r*ldc + c);
                    v0 += rs.x; v1 += rs.y;
                }
                if (OP == 2) {
                    v0 = 0.5f*v0*(1.0f + erff(v0*0.70710678118654752f));
                    v1 = 0.5f*v1*(1.0f + erff(v1*0.70710678118654752f));
                }
                *(float2*)(C + (size_t)r*ldc + c) = make_float2(v0, v1);
            }
        }
    }
}

// ------------------------------------------------------ spatial attention ----
__global__ void __launch_bounds__(256) spat_attn_kernel(const float* __restrict__ qkv,
                                                        float* __restrict__ out)
{
    __shared__ float Q[16][484];
    __shared__ float P[16][17];
    int g = blockIdx.x, tid = threadIdx.x;
    const float* src = qkv + (size_t)g*16*QW;
    for (int t = tid; t < 16*QW; t += 256) Q[t/QW][t%QW] = src[t];
    __syncthreads();
    int r = tid >> 4, c = tid & 15;
    float s = 0.f;
    #pragma unroll 8
    for (int k = 0; k < 160; k += 4) {
        float4 q4 = *(float4*)&Q[r][k];
        float4 k4 = *(float4*)&Q[c][160 + k];
        s += q4.x*k4.x + q4.y*k4.y + q4.z*k4.z + q4.w*k4.w;
    }
    s *= 0.07905694150420949f;
    float m = s;
    #pragma unroll
    for (int msk = 8; msk; msk >>= 1) m = fmaxf(m, __shfl_xor_sync(0xffffffffu, m, msk));
    float p = expf(s - m);
    float sum = p;
    #pragma unroll
    for (int msk = 8; msk; msk >>= 1) sum += __shfl_xor_sync(0xffffffffu, sum, msk);
    P[r][c] = p / sum;
    __syncthreads();
    int c0 = (tid & 15)*10; r = tid >> 4;
    float acc[10] = {};
    #pragma unroll
    for (int j = 0; j < 16; j++) {
        float pv = P[r][j];
        #pragma unroll
        for (int q = 0; q < 10; q++) acc[q] += pv * Q[j][320 + c0 + q];
    }
    float* dst = out + (size_t)(g*16 + r)*DD + c0;
    #pragma unroll
    for (int q = 0; q < 10; q++) dst[q] = acc[q];
}

// --------------------------------------------------------- node attention ----
__global__ void __launch_bounds__(128) node_attn_kernel(const float* __restrict__ qkv,
                                                        float* __restrict__ out)
{
    __shared__ float Qs[32][164];
    __shared__ float KV[32][164];
    __shared__ float Ps[32][33];
    __shared__ float f_s[32], l_s[32];
    int qt = blockIdx.x;
    int g  = blockIdx.y;
    int b = g >> 4, s = g & 15;
    int tid = threadIdx.x;
    const size_t rowstride = (size_t)PSZ*QW;
    size_t base = (size_t)b*NNODE*QW + (size_t)s*QW;
    const float scale = 0.07905694150420949f;

    for (int t = tid; t < 32*160; t += 128) {
        int r = t/160, c = t%160;
        Qs[r][c] = qkv[base + (size_t)(qt*32 + r)*rowstride + c] * scale;
    }
    float O[4][10] = {};
    float mrow[2] = {-3.0e38f, -3.0e38f};
    float lrow[2] = {0.f, 0.f};
    int rg = tid >> 3, cg = tid & 7;
    int ro = (tid >> 4)*4, co = (tid & 15)*10;

    for (int kt = 0; kt < 16; kt++) {
        __syncthreads();
        for (int t = tid; t < 32*160; t += 128) {
            int r = t/160, c = t%160;
            KV[r][c] = qkv[base + (size_t)(kt*32 + r)*rowstride + 160 + c];
        }
        __syncthreads();
        float sv[2][4] = {};
        #pragma unroll 4
        for (int k = 0; k < 160; k += 4) {
            float4 q0 = *(float4*)&Qs[2*rg][k];
            float4 q1 = *(float4*)&Qs[2*rg + 1][k];
            #pragma unroll
            for (int j = 0; j < 4; j++) {
                float4 k4 = *(float4*)&KV[cg + 8*j][k];
                sv[0][j] += q0.x*k4.x + q0.y*k4.y + q0.z*k4.z + q0.w*k4.w;
                sv[1][j] += q1.x*k4.x + q1.y*k4.y + q1.z*k4.z + q1.w*k4.w;
            }
        }
        #pragma unroll
        for (int ii = 0; ii < 2; ii++) {
            int r = 2*rg + ii;
            float mt = fmaxf(fmaxf(sv[ii][0], sv[ii][1]), fmaxf(sv[ii][2], sv[ii][3]));
            #pragma unroll
            for (int msk = 4; msk; msk >>= 1)
                mt = fmaxf(mt, __shfl_xor_sync(0xffffffffu, mt, msk));
            float mn = fmaxf(mrow[ii], mt);
            float f  = expf(mrow[ii] - mn);
            float sum = 0.f;
            #pragma unroll
            for (int j = 0; j < 4; j++) {
                float p = expf(sv[ii][j] - mn);
                Ps[r][cg + 8*j] = p;
                sum += p;
            }
            #pragma unroll
            for (int msk = 4; msk; msk >>= 1)
                sum += __shfl_xor_sync(0xffffffffu, sum, msk);
            lrow[ii] = lrow[ii]*f + sum;
            mrow[ii] = mn;
            if (cg == 0) f_s[r] = f;
        }
        __syncthreads();
        for (int t = tid; t < 32*160; t += 128) {
            int r = t/160, c = t%160;
            KV[r][c] = qkv[base + (size_t)(kt*32 + r)*rowstride + 320 + c];
        }
        __syncthreads();
        float fo[4];
        #pragma unroll
        for (int i = 0; i < 4; i++) {
            fo[i] = f_s[ro + i];
            #pragma unroll
            for (int c = 0; c < 10; c++) O[i][c] *= fo[i];
        }
        #pragma unroll 2
        for (int j = 0; j < 32; j++) {
            float pv[4];
            #pragma unroll
            for (int i = 0; i < 4; i++) pv[i] = Ps[ro + i][j];
            #pragma unroll
            for (int c = 0; c < 10; c += 2) {
                float2 v2 = *(float2*)&KV[j][co + c];
                #pragma unroll
                for (int i = 0; i < 4; i++) {
                    O[i][c]   += pv[i]*v2.x;
                    O[i][c+1] += pv[i]*v2.y;
                }
            }
        }
    }
    if (cg == 0) { l_s[2*rg] = lrow[0]; l_s[2*rg + 1] = lrow[1]; }
    __syncthreads();
    #pragma unroll
    for (int i = 0; i < 4; i++) {
        float inv = 1.0f / l_s[ro + i];
        size_t orow = ((size_t)b*NNODE + (size_t)(qt*32 + ro + i)*PSZ + s)*DD + co;
        #pragma unroll
        for (int c = 0; c < 10; c++) out[orow + c] = O[i][c]*inv;
    }
}

// --------------------------------------------------- scatter / regression ----
__global__ void zero_kernel(float* p, size_t n)
{
    size_t i = (size_t)blockIdx.x*blockDim.x + threadIdx.x;
    if (i < n) p[i] = 0.f;
}

__global__ void scatter_kernel(const float* __restrict__ rex, float* __restrict__ orig,
                               const int* __restrict__ ori, const int* __restrict__ reo)
{
    int i = blockIdx.x, b = blockIdx.y, d = threadIdx.x;
    orig[((size_t)b*NNODE + ori[i])*DD + d] = rex[((size_t)b*NNODE + reo[i])*DD + d];
}

__global__ void __launch_bounds__(256) pred_kernel(const float* __restrict__ orig,
                                                   const float* __restrict__ reg_w,
                                                   const float* __restrict__ reg_b,
                                                   float* __restrict__ out)
{
    __shared__ float T[32][164];
    __shared__ float Wsh[12*160];
    int n0 = blockIdx.x*32, b = blockIdx.y, tid = threadIdx.x;
    for (int t = tid; t < 12*160; t += 256) Wsh[t] = reg_w[t];
    for (int t = tid; t < 32*160; t += 256)
        T[t/160][t%160] = orig[((size_t)b*NNODE + n0 + t/160)*DD + t%160];
    __syncthreads();
    for (int t = tid; t < 384; t += 256) {
        int o = t/32, nn = t%32;
        float acc = reg_b[o];
        #pragma unroll 8
        for (int d = 0; d < 160; d++) acc += Wsh[o*160 + d]*T[nn][d];
        out[((size_t)(b*12 + o))*NNODE + n0 + nn] = acc;
    }
}

// ---------------------------------------------------------------- launch ----
extern "C" void kernel_launch(void* const* d_in, const int* in_sizes, int n_in,
                              void* d_out, int out_size)
{
    const float* x        = (const float*)d_in[0];
    const int*   te       = (const int*)  d_in[1];
    const int*   reo_all  = (const int*)  d_in[2];
    const int*   ori_p    = (const int*)  d_in[3];
    const int*   reo_p    = (const int*)  d_in[4];
    const float* node_emb = (const float*)d_in[5];
    const float* tod_emb  = (const float*)d_in[6];
    const float* dow_emb  = (const float*)d_in[7];
    const float* in_w     = (const float*)d_in[8];
    const float* in_b     = (const float*)d_in[9];
    const float* qkv_s_w  = (const float*)d_in[10];
    const float* qkv_s_b  = (const float*)d_in[11];
    const float* proj_s_w = (const float*)d_in[12];
    const float* proj_s_b = (const float*)d_in[13];
    const float* fc1_s_w  = (const float*)d_in[14];
    const float* fc1_s_b  = (const float*)d_in[15];
    const float* fc2_s_w  = (const float*)d_in[16];
    const float* fc2_s_b  = (const float*)d_in[17];
    const float* qkv_n_w  = (const float*)d_in[18];
    const float* qkv_n_b  = (const float*)d_in[19];
    const float* proj_n_w = (const float*)d_in[20];
    const float* proj_n_b = (const float*)d_in[21];
    const float* fc1_n_w  = (const float*)d_in[22];
    const float* fc1_n_b  = (const float*)d_in[23];
    const float* fc2_n_w  = (const float*)d_in[24];
    const float* fc2_n_b  = (const float*)d_in[25];
    const float* reg_w    = (const float*)d_in[26];
    const float* reg_b    = (const float*)d_in[27];
    float* out = (float*)d_out;

    int B = in_sizes[0] / (12*NNODE);
    int M = B*NNODE;

    float *rex, *ln, *tmp, *qkv;
    cudaGetSymbolAddress((void**)&rex, g_rex);
    cudaGetSymbolAddress((void**)&ln,  g_ln);
    cudaGetSymbolAddress((void**)&tmp, g_tmp);
    cudaGetSymbolAddress((void**)&qkv, g_qkv);

    embed_kernel<<<dim3(NNODE, B), DD>>>(x, te, reo_all, node_emb, tod_emb, dow_emb,
                                         in_w, in_b);

    for (int l = 0; l < 3; l++) {
        size_t oW3 = (size_t)l*DD*QW, ob3 = (size_t)l*QW;
        size_t oW1 = (size_t)l*DD*DD, ob1 = (size_t)l*DD;

        // --- spatial attention block ---
        ln_kernel<<<M/8, 256>>>(rex, ln, M);
        gemm_mma_kernel<0><<<dim3(M/128, 3), 256>>>(ln, qkv_s_w + oW3, qkv_s_b + ob3,
                                                    nullptr, qkv, QW, QW);
        spat_attn_kernel<<<M/16, 256>>>(qkv, tmp);
        gemm_mma_kernel<1><<<dim3(M/128, 1), 256>>>(tmp, proj_s_w + oW1, proj_s_b + ob1,
                                                    rex, rex, DD, DD);
        // --- spatial MLP ---
        ln_kernel<<<M/8, 256>>>(rex, ln, M);
        gemm_mma_kernel<2><<<dim3(M/128, 1), 256>>>(ln, fc1_s_w + oW1, fc1_s_b + ob1,
                                                    nullptr, tmp, DD, DD);
        gemm_mma_kernel<1><<<dim3(M/128, 1), 256>>>(tmp, fc2_s_w + oW1, fc2_s_b + ob1,
                                                    rex, rex, DD, DD);
        // --- node attention block ---
        ln_kernel<<<M/8, 256>>>(rex, ln, M);
        gemm_mma_kernel<0><<<dim3(M/128, 3), 256>>>(ln, qkv_n_w + oW3, qkv_n_b + ob3,
                                                    nullptr, qkv, QW, QW);
        node_attn_kernel<<<dim3(PNUM/32, B*PSZ), 128>>>(qkv, tmp);
        gemm_mma_kernel<1><<<dim3(M/128, 1), 256>>>(tmp, proj_n_w + oW1, proj_n_b + ob1,
                                                    rex, rex, DD, DD);
        // --- node MLP ---
        ln_kernel<<<M/8, 256>>>(rex, ln, M);
        gemm_mma_kernel<2><<<dim3(M/128, 1), 256>>>(ln, fc1_n_w + oW1, fc1_n_b + ob1,
                                                    nullptr, tmp, DD, DD);
        gemm_mma_kernel<1><<<dim3(M/128, 1), 256>>>(tmp, fc2_n_w + oW1, fc2_n_b + ob1,
                                                    rex, rex, DD, DD);
    }

    size_t tot = (size_t)M*DD;
    zero_kernel<<<(unsigned)((tot + 255)/256), 256>>>(ln, tot);
    scatter_kernel<<<dim3(NNODE, B), DD>>>(rex, ln, ori_p, reo_p);
    pred_kernel<<<dim3(NNODE/32, B), 256>>>(ln, reg_w, reg_b, out);
}

// round 4
// speedup vs baseline: 2.9133x; 2.2492x over previous
#include <cuda_runtime.h>
#include <math.h>
#include <stdint.h>

#define DD    160
#define QW    480      // 3*DD
#define NNODE 8192
#define PSZ   16
#define PNUM  512
#define MAXB  16

// ---------------- scratch (static device globals; no runtime allocation) ----
static __device__ float g_rex[(size_t)MAXB*NNODE*DD];
static __device__ float g_ln [(size_t)MAXB*NNODE*DD];
static __device__ float g_tmp[(size_t)MAXB*NNODE*DD];
static __device__ float g_qkv[(size_t)MAXB*NNODE*QW];
static __device__ float g_wr [921600];                  // tf32-rounded weights

// ------------------------------------------------------------- helpers -----
__device__ __forceinline__ unsigned f2tf32(float f)
{
    unsigned r;
    asm("cvt.rna.tf32.f32 %0, %1;" : "=r"(r) : "f"(f));
    return r;
}
__device__ __forceinline__ float tf32r(float f) { return __uint_as_float(f2tf32(f)); }

__device__ __forceinline__ void mma8(float* c, const unsigned* a, const unsigned* b)
{
    asm volatile(
        "mma.sync.aligned.m16n8k8.row.col.f32.tf32.tf32.f32 "
        "{%0,%1,%2,%3}, {%4,%5,%6,%7}, {%8,%9}, {%0,%1,%2,%3};\n"
        : "+f"(c[0]), "+f"(c[1]), "+f"(c[2]), "+f"(c[3])
        : "r"(a[0]), "r"(a[1]), "r"(a[2]), "r"(a[3]), "r"(b[0]), "r"(b[1]));
}

#define CP16(dst, src) \
    asm volatile("cp.async.cg.shared.global [%0], [%1], 16;\n" :: "r"(dst), "l"(src))
#define CP_COMMIT() asm volatile("cp.async.commit_group;\n")
#define CP_WAIT0()  asm volatile("cp.async.wait_group 0;\n")

// ----------------------------------------------------- weight rounding -----
__global__ void round_weights_kernel(const float* __restrict__ qs, const float* __restrict__ ps,
                                     const float* __restrict__ f1s, const float* __restrict__ f2s,
                                     const float* __restrict__ qn, const float* __restrict__ pn,
                                     const float* __restrict__ f1n, const float* __restrict__ f2n)
{
    int i = blockIdx.x*256 + threadIdx.x;
    if (i >= 921600) return;
    int j = i; float v;
    if (j < 460800) {
        if      (j < 230400) v = qs[j];
        else if (j < 307200) v = ps[j - 230400];
        else if (j < 384000) v = f1s[j - 307200];
        else                 v = f2s[j - 384000];
    } else {
        j -= 460800;
        if      (j < 230400) v = qn[j];
        else if (j < 307200) v = pn[j - 230400];
        else if (j < 384000) v = f1n[j - 307200];
        else                 v = f2n[j - 384000];
    }
    g_wr[i] = __uint_as_float(f2tf32(v));
}

// ---------------------------------------------------------------- embed ----
__global__ void embed_kernel(const float* __restrict__ x, const int* __restrict__ te,
                             const int* __restrict__ reo_all,
                             const float* __restrict__ node_emb,
                             const float* __restrict__ tod_emb,
                             const float* __restrict__ dow_emb,
                             const float* __restrict__ in_w,
                             const float* __restrict__ in_b)
{
    int j = blockIdx.x, b = blockIdx.y, o = threadIdx.x;
    __shared__ float x1[12][3];
    int n = reo_all[j];
    if (o < 12) {
        int p = o;
        size_t base = ((size_t)(b*12 + p))*NNODE + n;
        x1[p][0] = x[base];
        x1[p][1] = (float)te[base*2 + 0] * (1.0f/288.0f);
        x1[p][2] = (float)te[base*2 + 1] * (1.0f/7.0f);
    }
    __syncthreads();
    float v;
    size_t tb = (((size_t)(b*12 + 11))*NNODE + n)*2;
    if (o < 64) {
        v = in_b[o];
        #pragma unroll
        for (int c = 0; c < 3; c++)
            #pragma unroll
            for (int p = 0; p < 12; p++)
                v += x1[p][c] * in_w[(c*12 + p)*64 + o];
    } else if (o < 96) {
        v = tod_emb[te[tb + 0]*32 + (o - 64)];
    } else if (o < 128) {
        v = dow_emb[te[tb + 1]*32 + (o - 96)];
    } else {
        v = node_emb[(size_t)n*32 + (o - 128)];
    }
    g_rex[((size_t)b*NNODE + j)*DD + o] = v;
}

// ------------------------------------------------------------- layernorm ----
// output rounded to tf32 (it only feeds tf32 GEMM A operands)
__global__ void ln_kernel(const float* __restrict__ x, float* __restrict__ y, int M)
{
    int row  = blockIdx.x*8 + (threadIdx.x >> 5);
    int lane = threadIdx.x & 31;
    if (row >= M) return;
    const float* xr = x + (size_t)row*DD;
    float v[5]; float s = 0.f;
    #pragma unroll
    for (int j = 0; j < 5; j++) { v[j] = xr[lane + 32*j]; s += v[j]; }
    #pragma unroll
    for (int m = 16; m; m >>= 1) s += __shfl_xor_sync(0xffffffffu, s, m);
    float mean = s * (1.0f/160.0f);
    float q = 0.f;
    #pragma unroll
    for (int j = 0; j < 5; j++) { float d = v[j]-mean; q += d*d; }
    #pragma unroll
    for (int m = 16; m; m >>= 1) q += __shfl_xor_sync(0xffffffffu, q, m);
    float w = rsqrtf(q * (1.0f/160.0f) + 1e-6f);
    float* yr = y + (size_t)row*DD;
    #pragma unroll
    for (int j = 0; j < 5; j++) yr[lane + 32*j] = tf32r((v[j]-mean)*w);
}

// ------------------------------------------------------------------ gemm ----
// operands pre-rounded to tf32 by producers; cp.async double-buffered
// OP: 1 = bias + residual, 2 = bias + exact gelu (+tf32 round), 3 = bias (+tf32 round)
template<int OP>
__global__ void __launch_bounds__(256, 2) gemm_mma_kernel(
    const float* __restrict__ A, const float* __restrict__ W,
    const float* __restrict__ bias, const float* __restrict__ Rsd,
    float* __restrict__ C, int ldw, int ldc)
{
    extern __shared__ float sm[];
    float* As = sm;                    // [2][128][36]
    float* Bs = sm + 2*128*36;         // [2][32][168]  (Bs[k][n])
    const int tid = threadIdx.x, lane = tid & 31, wid = tid >> 5;
    const int warp_m = wid >> 2, warp_n = wid & 3;
    const int row0 = blockIdx.x*128, colbase = blockIdx.y*160;

    unsigned sAs = (unsigned)__cvta_generic_to_shared(As);
    unsigned sBs = (unsigned)__cvta_generic_to_shared(Bs);

    float acc[4][5][4] = {};

    // tile loader: K-tile k0 into buffer buf
    auto load_tile = [&](int k0, int buf) {
        const float* Ab = A + (size_t)row0*DD + k0;
        #pragma unroll
        for (int i = 0; i < 4; i++) {
            int idx = tid + i*256; int r = idx >> 3, c4 = idx & 7;
            CP16(sAs + (unsigned)((buf*128*36 + r*36 + c4*4)*4),
                 Ab + (size_t)r*DD + c4*4);
        }
        const float* Wb = W + (size_t)k0*ldw + colbase;
        #pragma unroll
        for (int i = 0; i < 5; i++) {
            int idx = tid + i*256; int r = idx/40, c4 = idx%40;
            CP16(sBs + (unsigned)((buf*32*168 + r*168 + c4*4)*4),
                 Wb + (size_t)r*ldw + c4*4);
        }
    };

    load_tile(0, 0);
    CP_COMMIT();

    for (int t = 0; t < 5; t++) {
        CP_WAIT0();
        __syncthreads();
        if (t < 4) { load_tile((t + 1)*32, (t + 1) & 1); CP_COMMIT(); }
        const float* Ab = As + (t & 1)*128*36;
        const float* Bb = Bs + (t & 1)*32*168;
        #pragma unroll
        for (int ks = 0; ks < 4; ks++) {
            unsigned af[4][4], bf[5][2];
            int arow = warp_m*64 + (lane >> 2);
            int kc   = ks*8 + (lane & 3);
            #pragma unroll
            for (int i = 0; i < 4; i++) {
                af[i][0] = __float_as_uint(Ab[(arow + i*16    )*36 + kc]);
                af[i][1] = __float_as_uint(Ab[(arow + i*16 + 8)*36 + kc]);
                af[i][2] = __float_as_uint(Ab[(arow + i*16    )*36 + kc + 4]);
                af[i][3] = __float_as_uint(Ab[(arow + i*16 + 8)*36 + kc + 4]);
            }
            int bn = warp_n*40 + (lane >> 2);
            #pragma unroll
            for (int j = 0; j < 5; j++) {
                bf[j][0] = __float_as_uint(Bb[(kc    )*168 + bn + j*8]);
                bf[j][1] = __float_as_uint(Bb[(kc + 4)*168 + bn + j*8]);
            }
            #pragma unroll
            for (int i = 0; i < 4; i++)
                #pragma unroll
                for (int j = 0; j < 5; j++)
                    mma8(acc[i][j], af[i], bf[j]);
        }
    }

    int rw = row0 + warp_m*64 + (lane >> 2);
    int cw = colbase + warp_n*40 + 2*(lane & 3);
    #pragma unroll
    for (int j = 0; j < 5; j++) {
        int c = cw + j*8;
        float b0 = bias[c], b1 = bias[c + 1];
        #pragma unroll
        for (int i = 0; i < 4; i++) {
            #pragma unroll
            for (int h = 0; h < 2; h++) {
                int r = rw + i*16 + h*8;
                float v0 = acc[i][j][2*h + 0] + b0;
                float v1 = acc[i][j][2*h + 1] + b1;
                if (OP == 1) {
                    float2 rs = *(const float2*)(Rsd + (size_t)r*ldc + c);
                    v0 += rs.x; v1 += rs.y;
                }
                if (OP == 2) {
                    v0 = tf32r(0.5f*v0*(1.0f + erff(v0*0.70710678118654752f)));
                    v1 = tf32r(0.5f*v1*(1.0f + erff(v1*0.70710678118654752f)));
                }
                if (OP == 3) { v0 = tf32r(v0); v1 = tf32r(v1); }
                *(float2*)(C + (size_t)r*ldc + c) = make_float2(v0, v1);
            }
        }
    }
}

// ------------------------------------------------------ spatial attention ----
__global__ void __launch_bounds__(256) spat_attn_kernel(const float* __restrict__ qkv,
                                                        float* __restrict__ out)
{
    __shared__ float Q[16][484];
    __shared__ float P[16][17];
    int g = blockIdx.x, tid = threadIdx.x;
    const float* src = qkv + (size_t)g*16*QW;
    for (int t = tid; t < 16*QW; t += 256) Q[t/QW][t%QW] = src[t];
    __syncthreads();
    int r = tid >> 4, c = tid & 15;
    float s = 0.f;
    #pragma unroll 8
    for (int k = 0; k < 160; k += 4) {
        float4 q4 = *(float4*)&Q[r][k];
        float4 k4 = *(float4*)&Q[c][160 + k];
        s += q4.x*k4.x + q4.y*k4.y + q4.z*k4.z + q4.w*k4.w;
    }
    s *= 0.07905694150420949f;
    float m = s;
    #pragma unroll
    for (int msk = 8; msk; msk >>= 1) m = fmaxf(m, __shfl_xor_sync(0xffffffffu, m, msk));
    float p = expf(s - m);
    float sum = p;
    #pragma unroll
    for (int msk = 8; msk; msk >>= 1) sum += __shfl_xor_sync(0xffffffffu, sum, msk);
    P[r][c] = p / sum;
    __syncthreads();
    int c0 = (tid & 15)*10; r = tid >> 4;
    float acc[10] = {};
    #pragma unroll
    for (int j = 0; j < 16; j++) {
        float pv = P[r][j];
        #pragma unroll
        for (int q = 0; q < 10; q++) acc[q] += pv * Q[j][320 + c0 + q];
    }
    float* dst = out + (size_t)(g*16 + r)*DD + c0;
    #pragma unroll
    for (int q = 0; q < 10; q++) dst[q] = tf32r(acc[q]);
}

// --------------------------------------------------------- node attention ----
// 32 queries/block, 512 keys streamed in 16 tiles; tf32 mma for QK^T and PV
__global__ void __launch_bounds__(128, 2) node_attn_kernel(const float* __restrict__ qkv,
                                                           float* __restrict__ out)
{
    extern __shared__ float sm[];
    float* Qs  = sm;                      // [32][164]
    float* Ks  = Qs + 32*164;             // [2][32][164]
    float* Vs  = Ks + 2*32*164;           // [2][32][168]
    float* Ps  = Vs + 2*32*168;           // [32][36]
    float* f_s = Ps + 32*36;              // [32]
    float* l_s = f_s + 32;                // [32]

    const int qt = blockIdx.x, g = blockIdx.y;
    const int b = g >> 4, s = g & 15;
    const int tid = threadIdx.x, lane = tid & 31, w = tid >> 5;
    const size_t rowstride = (size_t)PSZ*QW;
    const float* base = qkv + (size_t)b*NNODE*QW + (size_t)s*QW;
    const float scale = 0.07905694150420949f;

    unsigned sQ = (unsigned)__cvta_generic_to_shared(Qs);
    unsigned sK = (unsigned)__cvta_generic_to_shared(Ks);
    unsigned sV = (unsigned)__cvta_generic_to_shared(Vs);

    auto ldK = [&](int kt, int buf) {
        #pragma unroll
        for (int i = 0; i < 10; i++) {
            int idx = tid + i*128; int r = idx/40, c4 = idx%40;
            CP16(sK + (unsigned)((buf*32*164 + r*164 + c4*4)*4),
                 base + (size_t)(kt*32 + r)*rowstride + 160 + c4*4);
        }
    };
    auto ldV = [&](int kt, int buf) {
        #pragma unroll
        for (int i = 0; i < 10; i++) {
            int idx = tid + i*128; int r = idx/40, c4 = idx%40;
            CP16(sV + (unsigned)((buf*32*168 + r*168 + c4*4)*4),
                 base + (size_t)(kt*32 + r)*rowstride + 320 + c4*4);
        }
    };
    // Q load
    #pragma unroll
    for (int i = 0; i < 10; i++) {
        int idx = tid + i*128; int r = idx/40, c4 = idx%40;
        CP16(sQ + (unsigned)((r*164 + c4*4)*4),
             base + (size_t)(qt*32 + r)*rowstride + c4*4);
    }
    ldK(0, 0); ldV(0, 0);
    CP_COMMIT();

    float o[2][5][4] = {};
    float mrow = -3.0e38f, lrow = 0.f;     // softmax-layout state: row = tid>>2
    const int srow = tid >> 2, sgrp = tid & 3;

    for (int kt = 0; kt < 16; kt++) {
        CP_WAIT0();
        __syncthreads();
        if (kt < 15) { ldK(kt + 1, (kt + 1) & 1); ldV(kt + 1, (kt + 1) & 1); CP_COMMIT(); }
        const float* Kb = Ks + (kt & 1)*32*164;
        const float* Vb = Vs + (kt & 1)*32*168;

        // ---- S = Q @ K^T (warp w owns cols w*8..w*8+8) ----
        float sv[2][4] = {};
        #pragma unroll
        for (int ks = 0; ks < 20; ks++) {
            int ar = lane >> 2, kc = ks*8 + (lane & 3);
            unsigned af0[4], af1[4], bf[2];
            af0[0] = __float_as_uint(Qs[(ar     )*164 + kc]);
            af0[1] = __float_as_uint(Qs[(ar +  8)*164 + kc]);
            af0[2] = __float_as_uint(Qs[(ar     )*164 + kc + 4]);
            af0[3] = __float_as_uint(Qs[(ar +  8)*164 + kc + 4]);
            af1[0] = __float_as_uint(Qs[(ar + 16)*164 + kc]);
            af1[1] = __float_as_uint(Qs[(ar + 24)*164 + kc]);
            af1[2] = __float_as_uint(Qs[(ar + 16)*164 + kc + 4]);
            af1[3] = __float_as_uint(Qs[(ar + 24)*164 + kc + 4]);
            int bn = w*8 + (lane >> 2);
            bf[0] = __float_as_uint(Kb[bn*164 + kc]);
            bf[1] = __float_as_uint(Kb[bn*164 + kc + 4]);
            mma8(sv[0], af0, bf);
            mma8(sv[1], af1, bf);
        }
        // write scaled raw S
        #pragma unroll
        for (int i = 0; i < 2; i++) {
            int r0 = (lane >> 2) + 16*i;
            *(float2*)&Ps[(r0    )*36 + w*8 + 2*(lane & 3)] =
                make_float2(sv[i][0]*scale, sv[i][1]*scale);
            *(float2*)&Ps[(r0 + 8)*36 + w*8 + 2*(lane & 3)] =
                make_float2(sv[i][2]*scale, sv[i][3]*scale);
        }
        __syncthreads();

        // ---- online softmax: thread owns (srow, cols sgrp*8..+8) ----
        float4 v0 = *(float4*)&Ps[srow*36 + sgrp*8];
        float4 v1 = *(float4*)&Ps[srow*36 + sgrp*8 + 4];
        float mt = fmaxf(fmaxf(fmaxf(v0.x, v0.y), fmaxf(v0.z, v0.w)),
                         fmaxf(fmaxf(v1.x, v1.y), fmaxf(v1.z, v1.w)));
        mt = fmaxf(mt, __shfl_xor_sync(0xffffffffu, mt, 1));
        mt = fmaxf(mt, __shfl_xor_sync(0xffffffffu, mt, 2));
        float mn = fmaxf(mrow, mt);
        float f  = __expf(mrow - mn);
        float p0 = __expf(v0.x - mn), p1 = __expf(v0.y - mn);
        float p2 = __expf(v0.z - mn), p3 = __expf(v0.w - mn);
        float p4 = __expf(v1.x - mn), p5 = __expf(v1.y - mn);
        float p6 = __expf(v1.z - mn), p7 = __expf(v1.w - mn);
        float sum = p0 + p1 + p2 + p3 + p4 + p5 + p6 + p7;
        sum += __shfl_xor_sync(0xffffffffu, sum, 1);
        sum += __shfl_xor_sync(0xffffffffu, sum, 2);
        lrow = lrow*f + sum;
        mrow = mn;
        *(float4*)&Ps[srow*36 + sgrp*8] =
            make_float4(tf32r(p0), tf32r(p1), tf32r(p2), tf32r(p3));
        *(float4*)&Ps[srow*36 + sgrp*8 + 4] =
            make_float4(tf32r(p4), tf32r(p5), tf32r(p6), tf32r(p7));
        if (sgrp == 0) f_s[srow] = f;
        __syncthreads();

        // ---- rescale O, then O += P @ V (warp w owns cols w*40..w*40+40) ----
        #pragma unroll
        for (int i = 0; i < 2; i++)
            #pragma unroll
            for (int h = 0; h < 2; h++) {
                float fv = f_s[(lane >> 2) + 16*i + 8*h];
                #pragma unroll
                for (int j = 0; j < 5; j++) {
                    o[i][j][2*h    ] *= fv;
                    o[i][j][2*h + 1] *= fv;
                }
            }
        #pragma unroll
        for (int ks = 0; ks < 4; ks++) {
            int ar = lane >> 2, kc = ks*8 + (lane & 3);
            unsigned af0[4], af1[4], bf[5][2];
            af0[0] = __float_as_uint(Ps[(ar     )*36 + kc]);
            af0[1] = __float_as_uint(Ps[(ar +  8)*36 + kc]);
            af0[2] = __float_as_uint(Ps[(ar     )*36 + kc + 4]);
            af0[3] = __float_as_uint(Ps[(ar +  8)*36 + kc + 4]);
            af1[0] = __float_as_uint(Ps[(ar + 16)*36 + kc]);
            af1[1] = __float_as_uint(Ps[(ar + 24)*36 + kc]);
            af1[2] = __float_as_uint(Ps[(ar + 16)*36 + kc + 4]);
            af1[3] = __float_as_uint(Ps[(ar + 24)*36 + kc + 4]);
            int bn = w*40 + (lane >> 2);
            #pragma unroll
            for (int j = 0; j < 5; j++) {
                bf[j][0] = __float_as_uint(Vb[(kc    )*168 + bn + j*8]);
                bf[j][1] = __float_as_uint(Vb[(kc + 4)*168 + bn + j*8]);
            }
            #pragma unroll
            for (int j = 0; j < 5; j++) { mma8(o[0][j], af0, bf[j]); mma8(o[1][j], af1, bf[j]); }
        }
    }

    if (sgrp == 0) l_s[srow] = lrow;
    __syncthreads();
    #pragma unroll
    for (int i = 0; i < 2; i++)
        #pragma unroll
        for (int h = 0; h < 2; h++) {
            int r = (lane >> 2) + 16*i + 8*h;
            float inv = 1.0f / l_s[r];
            size_t orow = ((size_t)b*NNODE + (size_t)(qt*32 + r)*PSZ + s)*DD;
            #pragma unroll
            for (int j = 0; j < 5; j++) {
                int c = w*40 + j*8 + 2*(lane & 3);
                *(float2*)(out + orow + c) =
                    make_float2(tf32r(o[i][j][2*h]*inv), tf32r(o[i][j][2*h + 1]*inv));
            }
        }
}

// --------------------------------------------------- scatter / regression ----
__global__ void zero_kernel(float* p, size_t n)
{
    size_t i = (size_t)blockIdx.x*blockDim.x + threadIdx.x;
    if (i < n) p[i] = 0.f;
}

__global__ void scatter_kernel(const float* __restrict__ rex, float* __restrict__ orig,
                               const int* __restrict__ ori, const int* __restrict__ reo)
{
    int i = blockIdx.x, b = blockIdx.y, d = threadIdx.x;
    orig[((size_t)b*NNODE + ori[i])*DD + d] = rex[((size_t)b*NNODE + reo[i])*DD + d];
}

__global__ void __launch_bounds__(256) pred_kernel(const float* __restrict__ orig,
                                                   const float* __restrict__ reg_w,
                                                   const float* __restrict__ reg_b,
                                                   float* __restrict__ out)
{
    __shared__ float T[32][164];
    __shared__ float Wsh[12*160];
    int n0 = blockIdx.x*32, b = blockIdx.y, tid = threadIdx.x;
    for (int t = tid; t < 12*160; t += 256) Wsh[t] = reg_w[t];
    for (int t = tid; t < 32*160; t += 256)
        T[t/160][t%160] = orig[((size_t)b*NNODE + n0 + t/160)*DD + t%160];
    __syncthreads();
    for (int t = tid; t < 384; t += 256) {
        int o = t/32, nn = t%32;
        float acc = reg_b[o];
        #pragma unroll 8
        for (int d = 0; d < 160; d++) acc += Wsh[o*160 + d]*T[nn][d];
        out[((size_t)(b*12 + o))*NNODE + n0 + nn] = acc;
    }
}

// ---------------------------------------------------------------- launch ----
extern "C" void kernel_launch(void* const* d_in, const int* in_sizes, int n_in,
                              void* d_out, int out_size)
{
    const float* x        = (const float*)d_in[0];
    const int*   te       = (const int*)  d_in[1];
    const int*   reo_all  = (const int*)  d_in[2];
    const int*   ori_p    = (const int*)  d_in[3];
    const int*   reo_p    = (const int*)  d_in[4];
    const float* node_emb = (const float*)d_in[5];
    const float* tod_emb  = (const float*)d_in[6];
    const float* dow_emb  = (const float*)d_in[7];
    const float* in_w     = (const float*)d_in[8];
    const float* in_b     = (const float*)d_in[9];
    const float* qkv_s_w  = (const float*)d_in[10];
    const float* qkv_s_b  = (const float*)d_in[11];
    const float* proj_s_w = (const float*)d_in[12];
    const float* proj_s_b = (const float*)d_in[13];
    const float* fc1_s_w  = (const float*)d_in[14];
    const float* fc1_s_b  = (const float*)d_in[15];
    const float* fc2_s_w  = (const float*)d_in[16];
    const float* fc2_s_b  = (const float*)d_in[17];
    const float* qkv_n_w  = (const float*)d_in[18];
    const float* qkv_n_b  = (const float*)d_in[19];
    const float* proj_n_w = (const float*)d_in[20];
    const float* proj_n_b = (const float*)d_in[21];
    const float* fc1_n_w  = (const float*)d_in[22];
    const float* fc1_n_b  = (const float*)d_in[23];
    const float* fc2_n_w  = (const float*)d_in[24];
    const float* fc2_n_b  = (const float*)d_in[25];
    const float* reg_w    = (const float*)d_in[26];
    const float* reg_b    = (const float*)d_in[27];
    float* out = (float*)d_out;

    int B = in_sizes[0] / (12*NNODE);
    int M = B*NNODE;

    float *rex, *ln, *tmp, *qkv, *wr;
    cudaGetSymbolAddress((void**)&rex, g_rex);
    cudaGetSymbolAddress((void**)&ln,  g_ln);
    cudaGetSymbolAddress((void**)&tmp, g_tmp);
    cudaGetSymbolAddress((void**)&qkv, g_qkv);
    cudaGetSymbolAddress((void**)&wr,  g_wr);

    const int GEMM_SMEM = (2*128*36 + 2*32*168)*4;           // 79872
    const int ATTN_SMEM = (32*164 + 2*32*164 + 2*32*168 + 32*36 + 64)*4; // 110848
    cudaFuncSetAttribute(gemm_mma_kernel<1>, cudaFuncAttributeMaxDynamicSharedMemorySize, GEMM_SMEM);
    cudaFuncSetAttribute(gemm_mma_kernel<2>, cudaFuncAttributeMaxDynamicSharedMemorySize, GEMM_SMEM);
    cudaFuncSetAttribute(gemm_mma_kernel<3>, cudaFuncAttributeMaxDynamicSharedMemorySize, GEMM_SMEM);
    cudaFuncSetAttribute(node_attn_kernel,   cudaFuncAttributeMaxDynamicSharedMemorySize, ATTN_SMEM);

    round_weights_kernel<<<3600, 256>>>(qkv_s_w, proj_s_w, fc1_s_w, fc2_s_w,
                                        qkv_n_w, proj_n_w, fc1_n_w, fc2_n_w);

    embed_kernel<<<dim3(NNODE, B), DD>>>(x, te, reo_all, node_emb, tod_emb, dow_emb,
                                         in_w, in_b);

    for (int l = 0; l < 3; l++) {
        const float* Wq_s = wr + 0      + (size_t)l*76800;
        const float* Wp_s = wr + 230400 + (size_t)l*25600;
        const float* W1_s = wr + 307200 + (size_t)l*25600;
        const float* W2_s = wr + 384000 + (size_t)l*25600;
        const float* Wq_n = wr + 460800 + (size_t)l*76800;
        const float* Wp_n = wr + 691200 + (size_t)l*25600;
        const float* W1_n = wr + 768000 + (size_t)l*25600;
        const float* W2_n = wr + 844800 + (size_t)l*25600;
        size_t ob3 = (size_t)l*QW, ob1 = (size_t)l*DD;

        // --- spatial attention block ---
        ln_kernel<<<M/8, 256>>>(rex, ln, M);
        gemm_mma_kernel<3><<<dim3(M/128, 3), 256, GEMM_SMEM>>>(ln, Wq_s, qkv_s_b + ob3,
                                                               nullptr, qkv, QW, QW);
        spat_attn_kernel<<<M/16, 256>>>(qkv, tmp);
        gemm_mma_kernel<1><<<dim3(M/128, 1), 256, GEMM_SMEM>>>(tmp, Wp_s, proj_s_b + ob1,
                                                               rex, rex, DD, DD);
        // --- spatial MLP ---
        ln_kernel<<<M/8, 256>>>(rex, ln, M);
        gemm_mma_kernel<2><<<dim3(M/128, 1), 256, GEMM_SMEM>>>(ln, W1_s, fc1_s_b + ob1,
                                                               nullptr, tmp, DD, DD);
        gemm_mma_kernel<1><<<dim3(M/128, 1), 256, GEMM_SMEM>>>(tmp, W2_s, fc2_s_b + ob1,
                                                               rex, rex, DD, DD);
        // --- node attention block ---
        ln_kernel<<<M/8, 256>>>(rex, ln, M);
        gemm_mma_kernel<3><<<dim3(M/128, 3), 256, GEMM_SMEM>>>(ln, Wq_n, qkv_n_b + ob3,
                                                               nullptr, qkv, QW, QW);
        node_attn_kernel<<<dim3(PNUM/32, B*PSZ), 128, ATTN_SMEM>>>(qkv, tmp);
        gemm_mma_kernel<1><<<dim3(M/128, 1), 256, GEMM_SMEM>>>(tmp, Wp_n, proj_n_b + ob1,
                                                               rex, rex, DD, DD);
        // --- node MLP ---
        ln_kernel<<<M/8, 256>>>(rex, ln, M);
        gemm_mma_kernel<2><<<dim3(M/128, 1), 256, GEMM_SMEM>>>(ln, W1_n, fc1_n_b + ob1,
                                                               nullptr, tmp, DD, DD);
        gemm_mma_kernel<1><<<dim3(M/128, 1), 256, GEMM_SMEM>>>(tmp, W2_n, fc2_n_b + ob1,
                                                               rex, rex, DD, DD);
    }

    size_t tot = (size_t)M*DD;
    zero_kernel<<<(unsigned)((tot + 255)/256), 256>>>(ln, tot);
    scatter_kernel<<<dim3(NNODE, B), DD>>>(rex, ln, ori_p, reo_p);
    pred_kernel<<<dim3(NNODE/32, B), 256>>>(ln, reg_w, reg_b, out);
}

// round 6
// speedup vs baseline: 2.9653x; 1.0178x over previous
#include <cuda_runtime.h>
#include <math.h>
#include <stdint.h>

#define DD    160
#define QW    480      // 3*DD
#define NNODE 8192
#define PSZ   16
#define PNUM  512
#define MAXB  16

// ---------------- scratch (static device globals; no runtime allocation) ----
static __device__ float g_rex[(size_t)MAXB*NNODE*DD];
static __device__ float g_ln [(size_t)MAXB*NNODE*DD];
static __device__ float g_tmp[(size_t)MAXB*NNODE*DD];
static __device__ float g_qkv[(size_t)MAXB*NNODE*QW];
static __device__ float g_wr [921600];   // tf32-rounded, transposed, pair-interleaved

// ------------------------------------------------------------- helpers -----
__device__ __forceinline__ unsigned f2tf32(float f)
{
    unsigned r;
    asm("cvt.rna.tf32.f32 %0, %1;" : "=r"(r) : "f"(f));
    return r;
}
__device__ __forceinline__ float tf32r(float f) { return __uint_as_float(f2tf32(f)); }

__device__ __forceinline__ void mma8(float* c, const unsigned* a, const unsigned* b)
{
    asm volatile(
        "mma.sync.aligned.m16n8k8.row.col.f32.tf32.tf32.f32 "
        "{%0,%1,%2,%3}, {%4,%5,%6,%7}, {%8,%9}, {%0,%1,%2,%3};\n"
        : "+f"(c[0]), "+f"(c[1]), "+f"(c[2]), "+f"(c[3])
        : "r"(a[0]), "r"(a[1]), "r"(a[2]), "r"(a[3]), "r"(b[0]), "r"(b[1]));
}

#define CP16(dst, src) \
    asm volatile("cp.async.cg.shared.global [%0], [%1], 16;\n" :: "r"(dst), "l"(src))
#define CP_COMMIT() asm volatile("cp.async.commit_group;\n")
#define CP_WAIT0()  asm volatile("cp.async.wait_group 0;\n")

// pair-interleave within each 8-group: k -> word, so (k, k+4) become adjacent
__device__ __forceinline__ int wk(int k)
{
    return (k & ~7) | ((k & 3) << 1) | ((k >> 2) & 1);
}

// ------------------------------------- weight prep: round+transpose+ilv -----
// output layout per matrix: Wt[n][wk(k)], row stride 160
__global__ void prep_weights_kernel(const float* __restrict__ qs, const float* __restrict__ ps,
                                    const float* __restrict__ f1s, const float* __restrict__ f2s,
                                    const float* __restrict__ qn, const float* __restrict__ pn,
                                    const float* __restrict__ f1n, const float* __restrict__ f2n)
{
    int i = blockIdx.x*256 + threadIdx.x;
    if (i >= 921600) return;
    int j = i;
    const float* src; int N, segbase;
    if (j < 460800) {
        if      (j < 230400) { src = qs;  N = 480; segbase = 0; }
        else if (j < 307200) { src = ps;  N = 160; segbase = 230400; j -= 230400; }
        else if (j < 384000) { src = f1s; N = 160; segbase = 307200; j -= 307200; }
        else                 { src = f2s; N = 160; segbase = 384000; j -= 384000; }
    } else {
        j -= 460800;
        if      (j < 230400) { src = qn;  N = 480; segbase = 460800; }
        else if (j < 307200) { src = pn;  N = 160; segbase = 691200; j -= 230400; }
        else if (j < 384000) { src = f1n; N = 160; segbase = 768000; j -= 307200; }
        else                 { src = f2n; N = 160; segbase = 844800; j -= 384000; }
    }
    int lsz = 160*N;
    int l2 = j / lsz, rem = j - l2*lsz;
    int k = rem / N, n = rem - k*N;
    g_wr[segbase + l2*lsz + n*160 + wk(k)] = __uint_as_float(f2tf32(src[j]));
}

// ---------------------------------------------------------------- embed ----
__global__ void embed_kernel(const float* __restrict__ x, const int* __restrict__ te,
                             const int* __restrict__ reo_all,
                             const float* __restrict__ node_emb,
                             const float* __restrict__ tod_emb,
                             const float* __restrict__ dow_emb,
                             const float* __restrict__ in_w,
                             const float* __restrict__ in_b)
{
    int j = blockIdx.x, b = blockIdx.y, o = threadIdx.x;
    __shared__ float x1[12][3];
    int n = reo_all[j];
    if (o < 12) {
        int p = o;
        size_t base = ((size_t)(b*12 + p))*NNODE + n;
        x1[p][0] = x[base];
        x1[p][1] = (float)te[base*2 + 0] * (1.0f/288.0f);
        x1[p][2] = (float)te[base*2 + 1] * (1.0f/7.0f);
    }
    __syncthreads();
    float v;
    size_t tb = (((size_t)(b*12 + 11))*NNODE + n)*2;
    if (o < 64) {
        v = in_b[o];
        #pragma unroll
        for (int c = 0; c < 3; c++)
            #pragma unroll
            for (int p = 0; p < 12; p++)
                v += x1[p][c] * in_w[(c*12 + p)*64 + o];
    } else if (o < 96) {
        v = tod_emb[te[tb + 0]*32 + (o - 64)];
    } else if (o < 128) {
        v = dow_emb[te[tb + 1]*32 + (o - 96)];
    } else {
        v = node_emb[(size_t)n*32 + (o - 128)];
    }
    g_rex[((size_t)b*NNODE + j)*DD + o] = v;
}

// ------------------------------------------------------------- layernorm ----
// standalone LN (used only once, after embed); output tf32-rounded
__global__ void ln_kernel(const float* __restrict__ x, float* __restrict__ y, int M)
{
    int row  = blockIdx.x*8 + (threadIdx.x >> 5);
    int lane = threadIdx.x & 31;
    if (row >= M) return;
    const float* xr = x + (size_t)row*DD;
    float v[5]; float s = 0.f;
    #pragma unroll
    for (int j = 0; j < 5; j++) { v[j] = xr[lane + 32*j]; s += v[j]; }
    #pragma unroll
    for (int m = 16; m; m >>= 1) s += __shfl_xor_sync(0xffffffffu, s, m);
    float mean = s * (1.0f/160.0f);
    float q = 0.f;
    #pragma unroll
    for (int j = 0; j < 5; j++) { float d = v[j]-mean; q += d*d; }
    #pragma unroll
    for (int m = 16; m; m >>= 1) q += __shfl_xor_sync(0xffffffffu, q, m);
    float w = rsqrtf(q * (1.0f/160.0f) + 1e-6f);
    float* yr = y + (size_t)row*DD;
    #pragma unroll
    for (int j = 0; j < 5; j++) yr[lane + 32*j] = tf32r((v[j]-mean)*w);
}

// ------------------------------------------------------------------ gemm ----
// A: row-major tf32-prerounded. Wt: [n][wk(k)] transposed+interleaved, stride 160.
// OP: 1 = bias + residual (optionally fused LN -> LnOut), 2 = bias+gelu, 3 = bias
template<int OP, int LNOUT>
__global__ void __launch_bounds__(256, 2) gemm_mma_kernel(
    const float* __restrict__ A, const float* __restrict__ Wt,
    const float* __restrict__ bias, const float* __restrict__ Rsd,
    float* __restrict__ C, float* __restrict__ LnOut, int ldc)
{
    extern __shared__ float sm[];
    float* As = sm;                    // [2][128][36]
    float* Bs = sm + 2*128*36;         // [2][160][40]  pair-interleaved k
    const int tid = threadIdx.x, lane = tid & 31, wid = tid >> 5;
    const int warp_m = wid >> 2, warp_n = wid & 3;
    const int row0 = blockIdx.x*128, colbase = blockIdx.y*160;

    unsigned sAs = (unsigned)__cvta_generic_to_shared(As);
    unsigned sBs = (unsigned)__cvta_generic_to_shared(Bs);

    float acc[4][5][4] = {};

    auto load_tile = [&](int k0, int buf) {
        const float* Ab = A + (size_t)row0*DD + k0;
        #pragma unroll
        for (int i = 0; i < 4; i++) {
            int idx = tid + i*256; int r = idx >> 3, c4 = idx & 7;
            CP16(sAs + (unsigned)((buf*128*36 + r*36 + c4*4)*4),
                 Ab + (size_t)r*DD + c4*4);
        }
        const float* Wb = Wt + (size_t)colbase*160 + k0;
        #pragma unroll
        for (int i = 0; i < 5; i++) {
            int idx = tid + i*256; int n = idx >> 3, c4 = idx & 7;
            CP16(sBs + (unsigned)((buf*160*40 + n*40 + c4*4)*4),
                 Wb + (size_t)n*160 + c4*4);
        }
    };

    load_tile(0, 0);
    CP_COMMIT();

    for (int t = 0; t < 5; t++) {
        CP_WAIT0();
        __syncthreads();
        if (t < 4) { load_tile((t + 1)*32, (t + 1) & 1); CP_COMMIT(); }
        const float* Ab = As + (t & 1)*128*36;
        const float* Bb = Bs + (t & 1)*160*40;
        #pragma unroll
        for (int ks = 0; ks < 4; ks++) {
            unsigned af[4][4], bf[5][2];
            int arow = warp_m*64 + (lane >> 2);
            int kc   = ks*8 + (lane & 3);
            #pragma unroll
            for (int i = 0; i < 4; i++) {
                af[i][0] = __float_as_uint(Ab[(arow + i*16    )*36 + kc]);
                af[i][1] = __float_as_uint(Ab[(arow + i*16 + 8)*36 + kc]);
                af[i][2] = __float_as_uint(Ab[(arow + i*16    )*36 + kc + 4]);
                af[i][3] = __float_as_uint(Ab[(arow + i*16 + 8)*36 + kc + 4]);
            }
            int bn = warp_n*40 + (lane >> 2);
            int bw = ks*8 + (lane & 3)*2;
            #pragma unroll
            for (int j = 0; j < 5; j++) {
                float2 b2 = *(const float2*)&Bb[(bn + j*8)*40 + bw];
                bf[j][0] = __float_as_uint(b2.x);
                bf[j][1] = __float_as_uint(b2.y);
            }
            #pragma unroll
            for (int i = 0; i < 4; i++)
                #pragma unroll
                for (int j = 0; j < 5; j++)
                    mma8(acc[i][j], af[i], bf[j]);
        }
    }

    if (LNOUT) __syncthreads();        // about to overwrite As/Bs with S
    float* S = sm;                     // [128][164]

    int rwl = warp_m*64 + (lane >> 2);
    int cwl = warp_n*40 + 2*(lane & 3);
    #pragma unroll
    for (int j = 0; j < 5; j++) {
        int cl = cwl + j*8, c = colbase + cl;
        float b0 = bias[c], b1 = bias[c + 1];
        #pragma unroll
        for (int i = 0; i < 4; i++) {
            #pragma unroll
            for (int h = 0; h < 2; h++) {
                int rl = rwl + i*16 + h*8, r = row0 + rl;
                float v0 = acc[i][j][2*h + 0] + b0;
                float v1 = acc[i][j][2*h + 1] + b1;
                if (OP == 1) {
                    float2 rs = *(const float2*)(Rsd + (size_t)r*ldc + c);
                    v0 += rs.x; v1 += rs.y;
                }
                if (OP == 2) {
                    v0 = tf32r(0.5f*v0*(1.0f + erff(v0*0.70710678118654752f)));
                    v1 = tf32r(0.5f*v1*(1.0f + erff(v1*0.70710678118654752f)));
                }
                if (OP == 3) { v0 = tf32r(v0); v1 = tf32r(v1); }
                *(float2*)(C + (size_t)r*ldc + c) = make_float2(v0, v1);
                if (LNOUT) { S[rl*164 + cl] = v0; S[rl*164 + cl + 1] = v1; }
            }
        }
    }

    if (LNOUT) {
        __syncthreads();
        // 8 warps x 16 rows: full LN per row, values stay in registers
        #pragma unroll 1
        for (int rr = 0; rr < 16; rr++) {
            int rl = wid*16 + rr;
            float vv[5]; float s = 0.f;
            #pragma unroll
            for (int q = 0; q < 5; q++) { vv[q] = S[rl*164 + lane + 32*q]; s += vv[q]; }
            #pragma unroll
            for (int m = 16; m; m >>= 1) s += __shfl_xor_sync(0xffffffffu, s, m);
            float mean = s * (1.0f/160.0f);
            float qv = 0.f;
            #pragma unroll
            for (int q = 0; q < 5; q++) { float d = vv[q]-mean; qv += d*d; }
            #pragma unroll
            for (int m = 16; m; m >>= 1) qv += __shfl_xor_sync(0xffffffffu, qv, m);
            float w = rsqrtf(qv * (1.0f/160.0f) + 1e-6f);
            float* yr = LnOut + (size_t)(row0 + rl)*DD;
            #pragma unroll
            for (int q = 0; q < 5; q++) yr[lane + 32*q] = tf32r((vv[q]-mean)*w);
        }
    }
}

// ------------------------------------------------------ spatial attention ----
__global__ void __launch_bounds__(256) spat_attn_kernel(const float* __restrict__ qkv,
                                                        float* __restrict__ out)
{
    __shared__ float Q[16][484];
    __shared__ float P[16][17];
    int g = blockIdx.x, tid = threadIdx.x;
    const float* src = qkv + (size_t)g*16*QW;
    for (int t = tid; t < 16*QW; t += 256) Q[t/QW][t%QW] = src[t];
    __syncthreads();
    int r = tid >> 4, c = tid & 15;
    float s = 0.f;
    #pragma unroll 8
    for (int k = 0; k < 160; k += 4) {
        float4 q4 = *(float4*)&Q[r][k];
        float4 k4 = *(float4*)&Q[c][160 + k];
        s += q4.x*k4.x + q4.y*k4.y + q4.z*k4.z + q4.w*k4.w;
    }
    s *= 0.07905694150420949f;
    float m = s;
    #pragma unroll
    for (int msk = 8; msk; msk >>= 1) m = fmaxf(m, __shfl_xor_sync(0xffffffffu, m, msk));
    float p = expf(s - m);
    float sum = p;
    #pragma unroll
    for (int msk = 8; msk; msk >>= 1) sum += __shfl_xor_sync(0xffffffffu, sum, msk);
    P[r][c] = p / sum;
    __syncthreads();
    int c0 = (tid & 15)*10; r = tid >> 4;
    float acc[10] = {};
    #pragma unroll
    for (int j = 0; j < 16; j++) {
        float pv = P[r][j];
        #pragma unroll
        for (int q = 0; q < 10; q++) acc[q] += pv * Q[j][320 + c0 + q];
    }
    float* dst = out + (size_t)(g*16 + r)*DD + c0;
    #pragma unroll
    for (int q = 0; q < 10; q++) dst[q] = tf32r(acc[q]);
}

// --------------------------------------------------------- node attention ----
// 64 queries/block (256 thr, 8 warps: 2m x 4n); K/V streamed in 32-row tiles
__global__ void __launch_bounds__(256, 1) node_attn_kernel(const float* __restrict__ qkv,
                                                           float* __restrict__ out)
{
    extern __shared__ float sm[];
    float* Qs  = sm;                      // [64][164]
    float* Ks  = Qs + 64*164;             // [2][32][164]
    float* Vs  = Ks + 2*32*164;           // [2][32][168]
    float* Ps  = Vs + 2*32*168;           // [64][36]
    float* f_s = Ps + 64*36;              // [64]
    float* l_s = f_s + 64;                // [64]

    const int qt = blockIdx.x, g = blockIdx.y;
    const int b = g >> 4, s = g & 15;
    const int tid = threadIdx.x, lane = tid & 31, w = tid >> 5;
    const int wm = w >> 2, wn = w & 3;
    const int ar = wm*32 + (lane >> 2);   // warp's A-row (used in loop + epilogue)
    const size_t rowstride = (size_t)PSZ*QW;
    const float* base = qkv + (size_t)b*NNODE*QW + (size_t)s*QW;
    const float scale = 0.07905694150420949f;

    unsigned sQ = (unsigned)__cvta_generic_to_shared(Qs);
    unsigned sK = (unsigned)__cvta_generic_to_shared(Ks);
    unsigned sV = (unsigned)__cvta_generic_to_shared(Vs);

    auto ldK = [&](int kt, int buf) {
        #pragma unroll
        for (int i = 0; i < 5; i++) {
            int idx = tid + i*256; int r = idx/40, c4 = idx%40;
            CP16(sK + (unsigned)((buf*32*164 + r*164 + c4*4)*4),
                 base + (size_t)(kt*32 + r)*rowstride + 160 + c4*4);
        }
    };
    auto ldV = [&](int kt, int buf) {
        #pragma unroll
        for (int i = 0; i < 5; i++) {
            int idx = tid + i*256; int r = idx/40, c4 = idx%40;
            CP16(sV + (unsigned)((buf*32*168 + r*168 + c4*4)*4),
                 base + (size_t)(kt*32 + r)*rowstride + 320 + c4*4);
        }
    };
    #pragma unroll
    for (int i = 0; i < 10; i++) {
        int idx = tid + i*256; int r = idx/40, c4 = idx%40;
        CP16(sQ + (unsigned)((r*164 + c4*4)*4),
             base + (size_t)(qt*64 + r)*rowstride + c4*4);
    }
    ldK(0, 0); ldV(0, 0);
    CP_COMMIT();

    float o[2][5][4] = {};
    float mrow = -3.0e38f, lrow = 0.f;
    const int srow = tid >> 2, sgrp = tid & 3;

    for (int kt = 0; kt < 16; kt++) {
        CP_WAIT0();
        __syncthreads();
        if (kt < 15) { ldK(kt + 1, (kt + 1) & 1); ldV(kt + 1, (kt + 1) & 1); CP_COMMIT(); }
        const float* Kb = Ks + (kt & 1)*32*164;
        const float* Vb = Vs + (kt & 1)*32*168;

        // ---- S(64x32) = Q @ K^T : warp (wm,wn) owns rows wm*32.., cols wn*8..
        float sv[2][4] = {};
        #pragma unroll
        for (int ks = 0; ks < 20; ks++) {
            int kc = ks*8 + (lane & 3);
            unsigned af0[4], af1[4], bf[2];
            af0[0] = __float_as_uint(Qs[(ar     )*164 + kc]);
            af0[1] = __float_as_uint(Qs[(ar +  8)*164 + kc]);
            af0[2] = __float_as_uint(Qs[(ar     )*164 + kc + 4]);
            af0[3] = __float_as_uint(Qs[(ar +  8)*164 + kc + 4]);
            af1[0] = __float_as_uint(Qs[(ar + 16)*164 + kc]);
            af1[1] = __float_as_uint(Qs[(ar + 24)*164 + kc]);
            af1[2] = __float_as_uint(Qs[(ar + 16)*164 + kc + 4]);
            af1[3] = __float_as_uint(Qs[(ar + 24)*164 + kc + 4]);
            int bn = wn*8 + (lane >> 2);
            bf[0] = __float_as_uint(Kb[bn*164 + kc]);
            bf[1] = __float_as_uint(Kb[bn*164 + kc + 4]);
            mma8(sv[0], af0, bf);
            mma8(sv[1], af1, bf);
        }
        #pragma unroll
        for (int i = 0; i < 2; i++) {
            int r0 = wm*32 + 16*i + (lane >> 2);
            *(float2*)&Ps[(r0    )*36 + wn*8 + 2*(lane & 3)] =
                make_float2(sv[i][0]*scale, sv[i][1]*scale);
            *(float2*)&Ps[(r0 + 8)*36 + wn*8 + 2*(lane & 3)] =
                make_float2(sv[i][2]*scale, sv[i][3]*scale);
        }
        __syncthreads();

        // ---- online softmax: thread owns (srow, cols sgrp*8..+8)
        float4 v0 = *(float4*)&Ps[srow*36 + sgrp*8];
        float4 v1 = *(float4*)&Ps[srow*36 + sgrp*8 + 4];
        float mt = fmaxf(fmaxf(fmaxf(v0.x, v0.y), fmaxf(v0.z, v0.w)),
                         fmaxf(fmaxf(v1.x, v1.y), fmaxf(v1.z, v1.w)));
        mt = fmaxf(mt, __shfl_xor_sync(0xffffffffu, mt, 1));
        mt = fmaxf(mt, __shfl_xor_sync(0xffffffffu, mt, 2));
        float mn = fmaxf(mrow, mt);
        float f  = __expf(mrow - mn);
        float p0 = __expf(v0.x - mn), p1 = __expf(v0.y - mn);
        float p2 = __expf(v0.z - mn), p3 = __expf(v0.w - mn);
        float p4 = __expf(v1.x - mn), p5 = __expf(v1.y - mn);
        float p6 = __expf(v1.z - mn), p7 = __expf(v1.w - mn);
        float sum = p0 + p1 + p2 + p3 + p4 + p5 + p6 + p7;
        sum += __shfl_xor_sync(0xffffffffu, sum, 1);
        sum += __shfl_xor_sync(0xffffffffu, sum, 2);
        lrow = lrow*f + sum;
        mrow = mn;
        *(float4*)&Ps[srow*36 + sgrp*8] =
            make_float4(tf32r(p0), tf32r(p1), tf32r(p2), tf32r(p3));
        *(float4*)&Ps[srow*36 + sgrp*8 + 4] =
            make_float4(tf32r(p4), tf32r(p5), tf32r(p6), tf32r(p7));
        if (sgrp == 0) f_s[srow] = f;
        __syncthreads();

        // ---- rescale O, then O(64x160) += P @ V : warp cols wn*40..
        #pragma unroll
        for (int i = 0; i < 2; i++)
            #pragma unroll
            for (int h = 0; h < 2; h++) {
                float fv = f_s[ar + 16*i + 8*h];
                #pragma unroll
                for (int j = 0; j < 5; j++) {
                    o[i][j][2*h    ] *= fv;
                    o[i][j][2*h + 1] *= fv;
                }
            }
        #pragma unroll
        for (int ks = 0; ks < 4; ks++) {
            int kc = ks*8 + (lane & 3);
            unsigned af0[4], af1[4], bf[5][2];
            af0[0] = __float_as_uint(Ps[(ar     )*36 + kc]);
            af0[1] = __float_as_uint(Ps[(ar +  8)*36 + kc]);
            af0[2] = __float_as_uint(Ps[(ar     )*36 + kc + 4]);
            af0[3] = __float_as_uint(Ps[(ar +  8)*36 + kc + 4]);
            af1[0] = __float_as_uint(Ps[(ar + 16)*36 + kc]);
            af1[1] = __float_as_uint(Ps[(ar + 24)*36 + kc]);
            af1[2] = __float_as_uint(Ps[(ar + 16)*36 + kc + 4]);
            af1[3] = __float_as_uint(Ps[(ar + 24)*36 + kc + 4]);
            int bn = wn*40 + (lane >> 2);
            #pragma unroll
            for (int j = 0; j < 5; j++) {
                bf[j][0] = __float_as_uint(Vb[(kc    )*168 + bn + j*8]);
                bf[j][1] = __float_as_uint(Vb[(kc + 4)*168 + bn + j*8]);
            }
            #pragma unroll
            for (int j = 0; j < 5; j++) { mma8(o[0][j], af0, bf[j]); mma8(o[1][j], af1, bf[j]); }
        }
    }

    if (sgrp == 0) l_s[srow] = lrow;
    __syncthreads();
    #pragma unroll
    for (int i = 0; i < 2; i++)
        #pragma unroll
        for (int h = 0; h < 2; h++) {
            int rl = ar + 16*i + 8*h;
            float inv = 1.0f / l_s[rl];
            size_t orow = ((size_t)b*NNODE + (size_t)(qt*64 + rl)*PSZ + s)*DD;
            #pragma unroll
            for (int j = 0; j < 5; j++) {
                int c = wn*40 + j*8 + 2*(lane & 3);
                *(float2*)(out + orow + c) =
                    make_float2(tf32r(o[i][j][2*h]*inv), tf32r(o[i][j][2*h + 1]*inv));
            }
        }
}

// --------------------------------------------------- scatter / regression ----
__global__ void zero_kernel(float* p, size_t n)
{
    size_t i = (size_t)blockIdx.x*blockDim.x + threadIdx.x;
    if (i < n) p[i] = 0.f;
}

__global__ void scatter_kernel(const float* __restrict__ rex, float* __restrict__ orig,
                               const int* __restrict__ ori, const int* __restrict__ reo)
{
    int i = blockIdx.x, b = blockIdx.y, d = threadIdx.x;
    orig[((size_t)b*NNODE + ori[i])*DD + d] = rex[((size_t)b*NNODE + reo[i])*DD + d];
}

__global__ void __launch_bounds__(256) pred_kernel(const float* __restrict__ orig,
                                                   const float* __restrict__ reg_w,
                                                   const float* __restrict__ reg_b,
                                                   float* __restrict__ out)
{
    __shared__ float T[32][164];
    __shared__ float Wsh[12*160];
    int n0 = blockIdx.x*32, b = blockIdx.y, tid = threadIdx.x;
    for (int t = tid; t < 12*160; t += 256) Wsh[t] = reg_w[t];
    for (int t = tid; t < 32*160; t += 256)
        T[t/160][t%160] = orig[((size_t)b*NNODE + n0 + t/160)*DD + t%160];
    __syncthreads();
    for (int t = tid; t < 384; t += 256) {
        int o = t/32, nn = t%32;
        float acc = reg_b[o];
        #pragma unroll 8
        for (int d = 0; d < 160; d++) acc += Wsh[o*160 + d]*T[nn][d];
        out[((size_t)(b*12 + o))*NNODE + n0 + nn] = acc;
    }
}

// ---------------------------------------------------------------- launch ----
extern "C" void kernel_launch(void* const* d_in, const int* in_sizes, int n_in,
                              void* d_out, int out_size)
{
    const float* x        = (const float*)d_in[0];
    const int*   te       = (const int*)  d_in[1];
    const int*   reo_all  = (const int*)  d_in[2];
    const int*   ori_p    = (const int*)  d_in[3];
    const int*   reo_p    = (const int*)  d_in[4];
    const float* node_emb = (const float*)d_in[5];
    const float* tod_emb  = (const float*)d_in[6];
    const float* dow_emb  = (const float*)d_in[7];
    const float* in_w     = (const float*)d_in[8];
    const float* in_b     = (const float*)d_in[9];
    const float* qkv_s_w  = (const float*)d_in[10];
    const float* qkv_s_b  = (const float*)d_in[11];
    const float* proj_s_w = (const float*)d_in[12];
    const float* proj_s_b = (const float*)d_in[13];
    const float* fc1_s_w  = (const float*)d_in[14];
    const float* fc1_s_b  = (const float*)d_in[15];
    const float* fc2_s_w  = (const float*)d_in[16];
    const float* fc2_s_b  = (const float*)d_in[17];
    const float* qkv_n_w  = (const float*)d_in[18];
    const float* qkv_n_b  = (const float*)d_in[19];
    const float* proj_n_w = (const float*)d_in[20];
    const float* proj_n_b = (const float*)d_in[21];
    const float* fc1_n_w  = (const float*)d_in[22];
    const float* fc1_n_b  = (const float*)d_in[23];
    const float* fc2_n_w  = (const float*)d_in[24];
    const float* fc2_n_b  = (const float*)d_in[25];
    const float* reg_w    = (const float*)d_in[26];
    const float* reg_b    = (const float*)d_in[27];
    float* out = (float*)d_out;

    int B = in_sizes[0] / (12*NNODE);
    int M = B*NNODE;

    float *rex, *ln, *tmp, *qkv, *wr;
    cudaGetSymbolAddress((void**)&rex, g_rex);
    cudaGetSymbolAddress((void**)&ln,  g_ln);
    cudaGetSymbolAddress((void**)&tmp, g_tmp);
    cudaGetSymbolAddress((void**)&qkv, g_qkv);
    cudaGetSymbolAddress((void**)&wr,  g_wr);

    const int GEMM_SMEM = (2*128*36 + 2*160*40)*4;                          // 88064
    const int ATTN_SMEM = (64*164 + 2*32*164 + 2*32*168 + 64*36 + 128)*4;   // 136704
    cudaFuncSetAttribute(gemm_mma_kernel<1,1>, cudaFuncAttributeMaxDynamicSharedMemorySize, GEMM_SMEM);
    cudaFuncSetAttribute(gemm_mma_kernel<1,0>, cudaFuncAttributeMaxDynamicSharedMemorySize, GEMM_SMEM);
    cudaFuncSetAttribute(gemm_mma_kernel<2,0>, cudaFuncAttributeMaxDynamicSharedMemorySize, GEMM_SMEM);
    cudaFuncSetAttribute(gemm_mma_kernel<3,0>, cudaFuncAttributeMaxDynamicSharedMemorySize, GEMM_SMEM);
    cudaFuncSetAttribute(node_attn_kernel,     cudaFuncAttributeMaxDynamicSharedMemorySize, ATTN_SMEM);

    prep_weights_kernel<<<3600, 256>>>(qkv_s_w, proj_s_w, fc1_s_w, fc2_s_w,
                                       qkv_n_w, proj_n_w, fc1_n_w, fc2_n_w);

    embed_kernel<<<dim3(NNODE, B), DD>>>(x, te, reo_all, node_emb, tod_emb, dow_emb,
                                         in_w, in_b);
    ln_kernel<<<M/8, 256>>>(rex, ln, M);    // only standalone LN (layer-0 entry)

    for (int l = 0; l < 3; l++) {
        const float* Wq_s = wr + 0      + (size_t)l*76800;
        const float* Wp_s = wr + 230400 + (size_t)l*25600;
        const float* W1_s = wr + 307200 + (size_t)l*25600;
        const float* W2_s = wr + 384000 + (size_t)l*25600;
        const float* Wq_n = wr + 460800 + (size_t)l*76800;
        const float* Wp_n = wr + 691200 + (size_t)l*25600;
        const float* W1_n = wr + 768000 + (size_t)l*25600;
        const float* W2_n = wr + 844800 + (size_t)l*25600;
        size_t ob3 = (size_t)l*QW, ob1 = (size_t)l*DD;

        // --- spatial attention block ---
        gemm_mma_kernel<3,0><<<dim3(M/128, 3), 256, GEMM_SMEM>>>(ln, Wq_s, qkv_s_b + ob3,
                                                                 nullptr, qkv, nullptr, QW);
        spat_attn_kernel<<<M/16, 256>>>(qkv, tmp);
        gemm_mma_kernel<1,1><<<dim3(M/128, 1), 256, GEMM_SMEM>>>(tmp, Wp_s, proj_s_b + ob1,
                                                                 rex, rex, ln, DD);
        // --- spatial MLP ---
        gemm_mma_kernel<2,0><<<dim3(M/128, 1), 256, GEMM_SMEM>>>(ln, W1_s, fc1_s_b + ob1,
                                                                 nullptr, tmp, nullptr, DD);
        gemm_mma_kernel<1,1><<<dim3(M/128, 1), 256, GEMM_SMEM>>>(tmp, W2_s, fc2_s_b + ob1,
                                                                 rex, rex, ln, DD);
        // --- node attention block ---
        gemm_mma_kernel<3,0><<<dim3(M/128, 3), 256, GEMM_SMEM>>>(ln, Wq_n, qkv_n_b + ob3,
                                                                 nullptr, qkv, nullptr, QW);
        node_attn_kernel<<<dim3(PNUM/64, B*PSZ), 256, ATTN_SMEM>>>(qkv, tmp);
        gemm_mma_kernel<1,1><<<dim3(M/128, 1), 256, GEMM_SMEM>>>(tmp, Wp_n, proj_n_b + ob1,
                                                                 rex, rex, ln, DD);
        // --- node MLP ---
        gemm_mma_kernel<2,0><<<dim3(M/128, 1), 256, GEMM_SMEM>>>(ln, W1_n, fc1_n_b + ob1,
                                                                 nullptr, tmp, nullptr, DD);
        if (l < 2)
            gemm_mma_kernel<1,1><<<dim3(M/128, 1), 256, GEMM_SMEM>>>(tmp, W2_n, fc2_n_b + ob1,
                                                                     rex, rex, ln, DD);
        else
            gemm_mma_kernel<1,0><<<dim3(M/128, 1), 256, GEMM_SMEM>>>(tmp, W2_n, fc2_n_b + ob1,
                                                                     rex, rex, nullptr, DD);
    }

    size_t tot = (size_t)M*DD;
    zero_kernel<<<(unsigned)((tot + 255)/256), 256>>>(ln, tot);
    scatter_kernel<<<dim3(NNODE, B), DD>>>(rex, ln, ori_p, reo_p);
    pred_kernel<<<dim3(NNODE/32, B), 256>>>(ln, reg_w, reg_b, out);
}